// round 2
// baseline (speedup 1.0000x reference)
#include <cuda_runtime.h>
#include <math.h>

// ---------------------------------------------------------------------------
// GiddAttention  B=2, L=2048, HID=2048, H=16, D=128  (fp32 baseline, round 1:
// mask read as 4-byte elements, nonzero == keep)
// ---------------------------------------------------------------------------
namespace {
constexpr int B_   = 2;
constexpr int L_   = 2048;
constexpr int HID_ = 2048;
constexpr int H_   = 16;
constexpr int D_   = 128;
constexpr int NT_  = B_ * L_;   // 4096 tokens
constexpr int BH_  = B_ * H_;   // 32 batch*head
constexpr float FAN_IN     = 0.022097086912079608f;  // 2048^-0.5
constexpr float ATTN_SCALE = 0.08838834764831845f;   // 128^-0.5
constexpr float SOFTCAP    = 30.0f;
constexpr float NEGF       = -3.402823466e38f;       // finfo(f32).min
constexpr float EPS_       = 1e-6f;
}

// scratch (static device globals; no runtime allocation)
__device__ float g_q[NT_ * HID_];
__device__ float g_k[NT_ * HID_];
__device__ float g_v[NT_ * HID_];
__device__ float g_qt[NT_ * HID_];   // [B,H,L,D]
__device__ float g_kt[NT_ * HID_];   // [B,H,L,D]
__device__ float g_vt[NT_ * HID_];   // [B,H,L,D]
__device__ float g_attn[NT_ * HID_]; // [B,L,H,D] == [B*L, HID]
__device__ float g_scores[(size_t)BH_ * L_ * L_];  // 512 MB

// ---------------------------------------------------------------------------
// Generic NT SGEMM: C[M,N] = alpha * A[M,K] @ B[N,K]^T  (both row-major)
// 128x128 tile, BK=8, 256 threads, 8x8 per-thread microtile.
// ---------------------------------------------------------------------------
__global__ __launch_bounds__(256, 2) void sgemm_nt(
    const float* __restrict__ A, const float* __restrict__ Bm,
    float* __restrict__ C, int M, int N, int K, float alpha)
{
    __shared__ float As[8][128];
    __shared__ float Bs[8][128];
    const int tid  = threadIdx.x;
    const int m0   = blockIdx.y * 128;
    const int n0   = blockIdx.x * 128;
    const int lrow = tid >> 1;
    const int lcol = (tid & 1) * 4;
    const int ty   = tid >> 4;
    const int tx   = tid & 15;
    const float* Ap = A  + (long long)(m0 + lrow) * K + lcol;
    const float* Bp = Bm + (long long)(n0 + lrow) * K + lcol;

    float acc[8][8] = {};
    for (int k0 = 0; k0 < K; k0 += 8) {
        float4 av = *(const float4*)(Ap + k0);
        float4 bv = *(const float4*)(Bp + k0);
        As[lcol + 0][lrow] = av.x; As[lcol + 1][lrow] = av.y;
        As[lcol + 2][lrow] = av.z; As[lcol + 3][lrow] = av.w;
        Bs[lcol + 0][lrow] = bv.x; Bs[lcol + 1][lrow] = bv.y;
        Bs[lcol + 2][lrow] = bv.z; Bs[lcol + 3][lrow] = bv.w;
        __syncthreads();
#pragma unroll
        for (int kk = 0; kk < 8; ++kk) {
            float af[8], bf[8];
            *(float4*)(af)     = *(const float4*)(&As[kk][ty * 8]);
            *(float4*)(af + 4) = *(const float4*)(&As[kk][ty * 8 + 4]);
            *(float4*)(bf)     = *(const float4*)(&Bs[kk][tx * 8]);
            *(float4*)(bf + 4) = *(const float4*)(&Bs[kk][tx * 8 + 4]);
#pragma unroll
            for (int i = 0; i < 8; ++i)
#pragma unroll
                for (int j = 0; j < 8; ++j)
                    acc[i][j] = fmaf(af[i], bf[j], acc[i][j]);
        }
        __syncthreads();
    }
#pragma unroll
    for (int i = 0; i < 8; ++i) {
        float* cp = C + (long long)(m0 + ty * 8 + i) * N + n0 + tx * 8;
        float4 o0 = make_float4(alpha * acc[i][0], alpha * acc[i][1],
                                alpha * acc[i][2], alpha * acc[i][3]);
        float4 o1 = make_float4(alpha * acc[i][4], alpha * acc[i][5],
                                alpha * acc[i][6], alpha * acc[i][7]);
        *(float4*)cp       = o0;
        *(float4*)(cp + 4) = o1;
    }
}

// ---------------------------------------------------------------------------
// Per-token post-processing: RMSNorm (flat hidden) + RoPE + bias, transpose to
// [B,H,L,D].  mode 0 = q (norm+rope, *ATTN_SCALE), 1 = k (norm+rope+bias),
// 2 = v (bias only).
// ---------------------------------------------------------------------------
__global__ __launch_bounds__(256) void qkv_post(
    const float* __restrict__ X, const float* __restrict__ w,
    const float* __restrict__ bias, const int* __restrict__ positions,
    float* __restrict__ Xt, int mode)
{
    __shared__ float sh[HID_];
    __shared__ float red[8];
    __shared__ float shInv[64];

    const int t = blockIdx.x;
    const int b = t >> 11;           // t / L_
    const int l = t & (L_ - 1);
    const float* x = X + (long long)t * HID_;

    if (threadIdx.x < 64) {
        // inv_freq[j] = 10000^{-2j/128} = 2^{-j * (2/128) * log2(10000)}
        shInv[threadIdx.x] =
            (float)exp2(-(double)threadIdx.x * 0.20762050593046014);
    }

    float ss = 0.f;
    for (int j = threadIdx.x; j < HID_; j += 256) {
        float v = x[j];
        sh[j] = v;
        ss += v * v;
    }
#pragma unroll
    for (int o = 16; o; o >>= 1) ss += __shfl_xor_sync(0xffffffffu, ss, o);
    if ((threadIdx.x & 31) == 0) red[threadIdx.x >> 5] = ss;
    __syncthreads();
    float tot = red[0] + red[1] + red[2] + red[3] +
                red[4] + red[5] + red[6] + red[7];
    const float rstd = rsqrtf(tot * (1.0f / HID_) + EPS_);
    const float p = (float)positions[t];

    for (int j = threadIdx.x; j < HID_; j += 256) {
        const int h = j >> 7;
        const int d = j & 127;
        float out;
        if (mode == 2) {
            out = sh[j] + bias[(h << 7) + d];
        } else {
            const float y = sh[j] * rstd * (1.f + w[j]);
            const int jh = d & 63;
            const float ang = p * shInv[jh];
            const float c = cosf(ang);
            const float s = sinf(ang);
            const int partner = (d < 64) ? j + 64 : j - 64;
            const float y2 = sh[partner] * rstd * (1.f + w[partner]);
            out = (d < 64) ? (y * c - y2 * s) : (y * c + y2 * s);
            if (mode == 0) out *= ATTN_SCALE;
            else           out += bias[(h << 7) + d];
        }
        Xt[(((long long)(b * H_ + h)) * L_ + l) * D_ + d] = out;
    }
}

// ---------------------------------------------------------------------------
// Batched scores: S[bh,q,k] = softcap(Qt[bh] @ Kt[bh]^T) with mask epilogue.
// Qt pre-scaled by D^-0.5. grid (L/128, L/128, BH).
// mask: 4-byte elements (bool widened to int32/float32); nonzero == keep.
// ---------------------------------------------------------------------------
__global__ __launch_bounds__(256, 2) void scores_kernel(
    const float* __restrict__ Qt, const float* __restrict__ Kt,
    const unsigned int* __restrict__ mask, float* __restrict__ S)
{
    __shared__ float As[8][128];
    __shared__ float Bs[8][128];
    const int bh = blockIdx.z;
    const int b  = bh >> 4;
    const int tid  = threadIdx.x;
    const int m0   = blockIdx.y * 128;
    const int n0   = blockIdx.x * 128;
    const int lrow = tid >> 1;
    const int lcol = (tid & 1) * 4;
    const int ty   = tid >> 4;
    const int tx   = tid & 15;
    const float* Ap = Qt + (long long)bh * L_ * D_ + (long long)(m0 + lrow) * D_ + lcol;
    const float* Bp = Kt + (long long)bh * L_ * D_ + (long long)(n0 + lrow) * D_ + lcol;

    float acc[8][8] = {};
    for (int k0 = 0; k0 < D_; k0 += 8) {
        float4 av = *(const float4*)(Ap + k0);
        float4 bv = *(const float4*)(Bp + k0);
        As[lcol + 0][lrow] = av.x; As[lcol + 1][lrow] = av.y;
        As[lcol + 2][lrow] = av.z; As[lcol + 3][lrow] = av.w;
        Bs[lcol + 0][lrow] = bv.x; Bs[lcol + 1][lrow] = bv.y;
        Bs[lcol + 2][lrow] = bv.z; Bs[lcol + 3][lrow] = bv.w;
        __syncthreads();
#pragma unroll
        for (int kk = 0; kk < 8; ++kk) {
            float af[8], bf[8];
            *(float4*)(af)     = *(const float4*)(&As[kk][ty * 8]);
            *(float4*)(af + 4) = *(const float4*)(&As[kk][ty * 8 + 4]);
            *(float4*)(bf)     = *(const float4*)(&Bs[kk][tx * 8]);
            *(float4*)(bf + 4) = *(const float4*)(&Bs[kk][tx * 8 + 4]);
#pragma unroll
            for (int i = 0; i < 8; ++i)
#pragma unroll
                for (int j = 0; j < 8; ++j)
                    acc[i][j] = fmaf(af[i], bf[j], acc[i][j]);
        }
        __syncthreads();
    }
    const unsigned int* mrow = mask + (long long)b * L_ * L_;
    float* Srow = S + (long long)bh * L_ * L_;
#pragma unroll
    for (int i = 0; i < 8; ++i) {
        const int q = m0 + ty * 8 + i;
#pragma unroll
        for (int j = 0; j < 8; ++j) {
            const int kc = n0 + tx * 8 + j;
            float s = acc[i][j];
            s = SOFTCAP * tanhf(s * (1.0f / SOFTCAP));
            if (mrow[(long long)q * L_ + kc] == 0u) s = NEGF;
            Srow[(long long)q * L_ + kc] = s;
        }
    }
}

// ---------------------------------------------------------------------------
// Row softmax in place: one block per row, 2048 elems, register-resident.
// ---------------------------------------------------------------------------
__global__ __launch_bounds__(256) void softmax_kernel(float* __restrict__ S)
{
    __shared__ float red[8];
    float* p = S + (long long)blockIdx.x * L_;
    float vals[8];
    float mx = -3.402823466e38f;
#pragma unroll
    for (int i = 0; i < 8; ++i) {
        vals[i] = p[threadIdx.x + i * 256];
        mx = fmaxf(mx, vals[i]);
    }
#pragma unroll
    for (int o = 16; o; o >>= 1) mx = fmaxf(mx, __shfl_xor_sync(0xffffffffu, mx, o));
    if ((threadIdx.x & 31) == 0) red[threadIdx.x >> 5] = mx;
    __syncthreads();
    mx = fmaxf(fmaxf(fmaxf(red[0], red[1]), fmaxf(red[2], red[3])),
               fmaxf(fmaxf(red[4], red[5]), fmaxf(red[6], red[7])));
    __syncthreads();
    float sum = 0.f;
#pragma unroll
    for (int i = 0; i < 8; ++i) {
        vals[i] = expf(vals[i] - mx);
        sum += vals[i];
    }
#pragma unroll
    for (int o = 16; o; o >>= 1) sum += __shfl_xor_sync(0xffffffffu, sum, o);
    if ((threadIdx.x & 31) == 0) red[threadIdx.x >> 5] = sum;
    __syncthreads();
    sum = red[0] + red[1] + red[2] + red[3] + red[4] + red[5] + red[6] + red[7];
    const float inv = 1.0f / sum;
#pragma unroll
    for (int i = 0; i < 8; ++i) p[threadIdx.x + i * 256] = vals[i] * inv;
}

// ---------------------------------------------------------------------------
// Batched NN GEMM: O[b,q,h,:] = P[bh] @ Vt[bh]  (M=L, N=D=128, K=L).
// grid (L/128, BH). Output scattered into [B,L,H,D].
// ---------------------------------------------------------------------------
__global__ __launch_bounds__(256, 2) void pv_kernel(
    const float* __restrict__ S, const float* __restrict__ Vt,
    float* __restrict__ O)
{
    __shared__ float As[8][128];
    __shared__ float Bs[8][128];
    const int bh = blockIdx.y;
    const int b = bh >> 4, h = bh & 15;
    const int tid  = threadIdx.x;
    const int m0   = blockIdx.x * 128;
    const int lrow = tid >> 1;
    const int lcol = (tid & 1) * 4;
    const int brow = tid >> 5;
    const int bcol = (tid & 31) * 4;
    const int ty   = tid >> 4;
    const int tx   = tid & 15;
    const float* Ap = S + (long long)bh * L_ * L_ + (long long)(m0 + lrow) * L_ + lcol;
    const float* Bp = Vt + (long long)bh * L_ * D_;

    float acc[8][8] = {};
    for (int k0 = 0; k0 < L_; k0 += 8) {
        float4 av = *(const float4*)(Ap + k0);
        As[lcol + 0][lrow] = av.x; As[lcol + 1][lrow] = av.y;
        As[lcol + 2][lrow] = av.z; As[lcol + 3][lrow] = av.w;
        float4 bv = *(const float4*)(Bp + (long long)(k0 + brow) * D_ + bcol);
        *(float4*)&Bs[brow][bcol] = bv;
        __syncthreads();
#pragma unroll
        for (int kk = 0; kk < 8; ++kk) {
            float af[8], bf[8];
            *(float4*)(af)     = *(const float4*)(&As[kk][ty * 8]);
            *(float4*)(af + 4) = *(const float4*)(&As[kk][ty * 8 + 4]);
            *(float4*)(bf)     = *(const float4*)(&Bs[kk][tx * 8]);
            *(float4*)(bf + 4) = *(const float4*)(&Bs[kk][tx * 8 + 4]);
#pragma unroll
            for (int i = 0; i < 8; ++i)
#pragma unroll
                for (int j = 0; j < 8; ++j)
                    acc[i][j] = fmaf(af[i], bf[j], acc[i][j]);
        }
        __syncthreads();
    }
#pragma unroll
    for (int i = 0; i < 8; ++i) {
        const int m = m0 + ty * 8 + i;
        float* cp = O + ((long long)(b * L_ + m) * H_ + h) * D_ + tx * 8;
        *(float4*)cp       = make_float4(acc[i][0], acc[i][1], acc[i][2], acc[i][3]);
        *(float4*)(cp + 4) = make_float4(acc[i][4], acc[i][5], acc[i][6], acc[i][7]);
    }
}

// ---------------------------------------------------------------------------
static float* sym_addr(const void* sym)
{
    void* p = nullptr;
    cudaGetSymbolAddress(&p, sym);
    return (float*)p;
}

extern "C" void kernel_launch(void* const* d_in, const int* in_sizes, int n_in,
                              void* d_out, int out_size)
{
    (void)in_sizes; (void)n_in; (void)out_size;
    const float* hs = (const float*)d_in[0];
    const float* Wq = (const float*)d_in[1];
    const float* Wk = (const float*)d_in[2];
    const float* Wv = (const float*)d_in[3];
    const float* Wo = (const float*)d_in[4];
    const float* qw = (const float*)d_in[5];
    const float* kw = (const float*)d_in[6];
    const float* kb = (const float*)d_in[7];
    const float* vb = (const float*)d_in[8];
    const int*   pos  = (const int*)d_in[9];
    const unsigned int* mask = (const unsigned int*)d_in[10];
    float* out = (float*)d_out;

    float* q    = sym_addr(g_q);
    float* k    = sym_addr(g_k);
    float* v    = sym_addr(g_v);
    float* qt   = sym_addr(g_qt);
    float* kt   = sym_addr(g_kt);
    float* vt   = sym_addr(g_vt);
    float* attn = sym_addr(g_attn);
    float* sc   = sym_addr(g_scores);

    dim3 blk(256);
    dim3 gProj(HID_ / 128, NT_ / 128);        // 16 x 32

    sgemm_nt<<<gProj, blk>>>(hs, Wq, q, NT_, HID_, HID_, FAN_IN);
    sgemm_nt<<<gProj, blk>>>(hs, Wk, k, NT_, HID_, HID_, FAN_IN);
    sgemm_nt<<<gProj, blk>>>(hs, Wv, v, NT_, HID_, HID_, FAN_IN);

    qkv_post<<<NT_, 256>>>(q, qw, nullptr, pos, qt, 0);
    qkv_post<<<NT_, 256>>>(k, kw, kb,      pos, kt, 1);
    qkv_post<<<NT_, 256>>>(v, nullptr, vb, pos, vt, 2);

    scores_kernel<<<dim3(L_ / 128, L_ / 128, BH_), blk>>>(qt, kt, mask, sc);
    softmax_kernel<<<BH_ * L_, 256>>>(sc);
    pv_kernel<<<dim3(L_ / 128, BH_), blk>>>(sc, vt, attn);

    sgemm_nt<<<gProj, blk>>>(attn, Wo, out, NT_, HID_, HID_, FAN_IN);
}

// round 4
// speedup vs baseline: 1.1191x; 1.1191x over previous
#include <cuda_runtime.h>
#include <cuda_bf16.h>
#include <math.h>
#include <cstdint>

// ---------------------------------------------------------------------------
// GiddAttention  B=2, L=2048, HID=2048, H=16, D=128
// Round 4: projection GEMMs on mma.sync bf16 (hi/lo split, fp32 accum).
// tcgen05 is unavailable: harness emits compute_103 PTX (no 'a' target).
// Attention core still fp32 FFMA (flash-fused MMA next round).
// ---------------------------------------------------------------------------
namespace {
constexpr int B_   = 2;
constexpr int L_   = 2048;
constexpr int HID_ = 2048;
constexpr int H_   = 16;
constexpr int D_   = 128;
constexpr int NT_  = B_ * L_;   // 4096
constexpr int BH_  = B_ * H_;   // 32
constexpr float FAN_IN     = 0.022097086912079608f;  // 2048^-0.5
constexpr float ATTN_SCALE = 0.08838834764831845f;   // 128^-0.5
constexpr float SOFTCAP    = 30.0f;
constexpr float NEGF       = -3.402823466e38f;
constexpr float EPS_       = 1e-6f;
}

// scratch
__device__ float g_q[NT_ * HID_];
__device__ float g_k[NT_ * HID_];
__device__ float g_v[NT_ * HID_];
__device__ float g_qt[NT_ * HID_];
__device__ float g_kt[NT_ * HID_];
__device__ float g_vt[NT_ * HID_];
__device__ float g_attn[NT_ * HID_];
__device__ float g_scores[(size_t)BH_ * L_ * L_];  // 512 MB
__device__ __nv_bfloat16 g_ahi[NT_ * HID_];
__device__ __nv_bfloat16 g_alo[NT_ * HID_];
__device__ __nv_bfloat16 g_whi[HID_ * HID_];
__device__ __nv_bfloat16 g_wlo[HID_ * HID_];

// ------------------------------ asm helpers --------------------------------
__device__ __forceinline__ uint32_t smem_u32(const void* p) {
    uint32_t a;
    asm("{ .reg .u64 t; cvta.to.shared.u64 t, %1; cvt.u32.u64 %0, t; }"
        : "=r"(a) : "l"(p));
    return a;
}
__device__ __forceinline__ void cp_async16(uint32_t dst, const void* src) {
    asm volatile("cp.async.cg.shared.global [%0], [%1], 16;"
                 :: "r"(dst), "l"(src) : "memory");
}
__device__ __forceinline__ void cp_commit() {
    asm volatile("cp.async.commit_group;" ::: "memory");
}
template <int N>
__device__ __forceinline__ void cp_wait() {
    asm volatile("cp.async.wait_group %0;" :: "n"(N) : "memory");
}
__device__ __forceinline__ void ldsm_x4(uint32_t& r0, uint32_t& r1,
                                        uint32_t& r2, uint32_t& r3, uint32_t a) {
    asm volatile("ldmatrix.sync.aligned.m8n8.x4.shared.b16 {%0,%1,%2,%3}, [%4];"
                 : "=r"(r0), "=r"(r1), "=r"(r2), "=r"(r3) : "r"(a));
}
__device__ __forceinline__ void mma_bf16(float* c, const uint32_t* a,
                                         const uint32_t* b) {
    asm volatile(
        "mma.sync.aligned.m16n8k16.row.col.f32.bf16.bf16.f32 "
        "{%0,%1,%2,%3}, {%4,%5,%6,%7}, {%8,%9}, {%0,%1,%2,%3};"
        : "+f"(c[0]), "+f"(c[1]), "+f"(c[2]), "+f"(c[3])
        : "r"(a[0]), "r"(a[1]), "r"(a[2]), "r"(a[3]), "r"(b[0]), "r"(b[1]));
}
// SW128 swizzle for 128B rows; col args are multiples of 8 bf16 (16B)
__device__ __forceinline__ uint32_t tile_addr(uint32_t base, int row, int col_bf16) {
    return base + row * 128 + ((((col_bf16 >> 3) ^ (row & 7)) << 4));
}

// ---------------------------------------------------------------------------
// fp32 -> (hi, lo) bf16 split
// ---------------------------------------------------------------------------
__global__ __launch_bounds__(256) void cvt_split(
    const float* __restrict__ x, __nv_bfloat16* __restrict__ hi,
    __nv_bfloat16* __restrict__ lo, int n4)
{
    int i = blockIdx.x * 256 + threadIdx.x;
    if (i >= n4) return;
    float4 v = ((const float4*)x)[i];
    __nv_bfloat16 h[4], l[4];
    const float* f = &v.x;
#pragma unroll
    for (int j = 0; j < 4; ++j) {
        h[j] = __float2bfloat16(f[j]);
        l[j] = __float2bfloat16(f[j] - __bfloat162float(h[j]));
    }
    ((uint2*)hi)[i] = *(uint2*)h;
    ((uint2*)lo)[i] = *(uint2*)l;
}

// ---------------------------------------------------------------------------
// split-bf16 NT GEMM on mma.sync:
//   C[4096,2048] = alpha * (Ahi+Alo)[4096,2048] @ (Bhi+Blo)[2048,2048]^T
// CTA 128x128, BK=64, 256 threads (8 warps, warp tile 64x32), cp.async
// double buffer.  SMEM buffer: Ahi 16K | Alo 16K | Bhi 16K | Blo 16K.
// ---------------------------------------------------------------------------
static constexpr int GEMM_SMEM = 2 * 65536;

__global__ __launch_bounds__(256, 1) void mma_gemm_nt(
    const __nv_bfloat16* __restrict__ Ahi, const __nv_bfloat16* __restrict__ Alo,
    const __nv_bfloat16* __restrict__ Bhi, const __nv_bfloat16* __restrict__ Blo,
    float* __restrict__ C, float alpha)
{
    extern __shared__ char smem[];
    const uint32_t sb = smem_u32(smem);
    const int tid = threadIdx.x;
    const int wid = tid >> 5, lid = tid & 31;
    const int wy = wid & 1, wx = wid >> 1;      // warp tile: (wy*64, wx*32)
    const int m0 = blockIdx.y * 128, n0 = blockIdx.x * 128;
    const int K = 2048, N = 2048;

    // per-lane ldmatrix row/col decomposition
    const int lr8 = lid & 7, sub = lid >> 3;
    const int a_row = wy * 64 + (sub & 1) * 8 + lr8;   // + i*16
    const int a_col = (sub >> 1) * 8;                  // + ks*16
    const int b_row = wx * 32 + (sub >> 1) * 8 + lr8;  // + jj*16
    const int b_col = (sub & 1) * 8;                   // + ks*16

    float acc[4][4][4] = {};

    // chunk loader: 1024 16B units per array, 4 per thread per array
    auto load_chunk = [&](int c) {
        const uint32_t base = sb + (c & 1) * 65536;
        const int k0 = c * 64;
#pragma unroll
        for (int v = 0; v < 4; ++v) {
            const int u = v * 256 + tid;
            const int row = u >> 3, c16 = u & 7;
            const uint32_t dst = base + row * 128 + (((c16 ^ (row & 7)) << 4));
            const long long ga = (long long)(m0 + row) * K + k0 + c16 * 8;
            const long long gb = (long long)(n0 + row) * K + k0 + c16 * 8;
            cp_async16(dst,          Ahi + ga);
            cp_async16(dst + 16384,  Alo + ga);
            cp_async16(dst + 32768,  Bhi + gb);
            cp_async16(dst + 49152,  Blo + gb);
        }
        cp_commit();
    };

    load_chunk(0);
    for (int c = 0; c < 32; ++c) {
        if (c < 31) load_chunk(c + 1);
        if (c < 31) cp_wait<1>(); else cp_wait<0>();
        __syncthreads();
        const uint32_t sA = sb + (c & 1) * 65536;
        const uint32_t sB = sA + 32768;
#pragma unroll
        for (int ks = 0; ks < 4; ++ks) {
            uint32_t af[2][4][4], bf[2][4][2];
#pragma unroll
            for (int i = 0; i < 4; ++i) {
                ldsm_x4(af[0][i][0], af[0][i][1], af[0][i][2], af[0][i][3],
                        tile_addr(sA,         a_row + i * 16, a_col + ks * 16));
                ldsm_x4(af[1][i][0], af[1][i][1], af[1][i][2], af[1][i][3],
                        tile_addr(sA + 16384, a_row + i * 16, a_col + ks * 16));
            }
#pragma unroll
            for (int jj = 0; jj < 2; ++jj) {
                uint32_t r0, r1, r2, r3;
                ldsm_x4(r0, r1, r2, r3,
                        tile_addr(sB,         b_row + jj * 16, b_col + ks * 16));
                bf[0][jj * 2][0] = r0; bf[0][jj * 2][1] = r1;
                bf[0][jj * 2 + 1][0] = r2; bf[0][jj * 2 + 1][1] = r3;
                ldsm_x4(r0, r1, r2, r3,
                        tile_addr(sB + 16384, b_row + jj * 16, b_col + ks * 16));
                bf[1][jj * 2][0] = r0; bf[1][jj * 2][1] = r1;
                bf[1][jj * 2 + 1][0] = r2; bf[1][jj * 2 + 1][1] = r3;
            }
#pragma unroll
            for (int i = 0; i < 4; ++i)
#pragma unroll
                for (int j = 0; j < 4; ++j)
                    mma_bf16(acc[i][j], af[0][i], bf[0][j]);
#pragma unroll
            for (int i = 0; i < 4; ++i)
#pragma unroll
                for (int j = 0; j < 4; ++j)
                    mma_bf16(acc[i][j], af[0][i], bf[1][j]);
#pragma unroll
            for (int i = 0; i < 4; ++i)
#pragma unroll
                for (int j = 0; j < 4; ++j)
                    mma_bf16(acc[i][j], af[1][i], bf[0][j]);
        }
        __syncthreads();
    }

    // epilogue
    const int g = lid >> 2, t = lid & 3;
#pragma unroll
    for (int i = 0; i < 4; ++i) {
        const int row = m0 + wy * 64 + i * 16 + g;
#pragma unroll
        for (int j = 0; j < 4; ++j) {
            const int col = n0 + wx * 32 + j * 8 + t * 2;
            float2 v0 = make_float2(alpha * acc[i][j][0], alpha * acc[i][j][1]);
            float2 v1 = make_float2(alpha * acc[i][j][2], alpha * acc[i][j][3]);
            *(float2*)(C + (long long)row * N + col)       = v0;
            *(float2*)(C + (long long)(row + 8) * N + col) = v1;
        }
    }
}

// ---------------------------------------------------------------------------
// Per-token post: RMSNorm + RoPE + bias, transpose to [B,H,L,D].
// ---------------------------------------------------------------------------
__global__ __launch_bounds__(256) void qkv_post(
    const float* __restrict__ X, const float* __restrict__ w,
    const float* __restrict__ bias, const int* __restrict__ positions,
    float* __restrict__ Xt, int mode)
{
    __shared__ float sh[HID_];
    __shared__ float red[8];
    __shared__ float shInv[64];

    const int t = blockIdx.x;
    const int b = t >> 11;
    const int l = t & (L_ - 1);
    const float* x = X + (long long)t * HID_;

    if (threadIdx.x < 64)
        shInv[threadIdx.x] =
            (float)exp2(-(double)threadIdx.x * 0.20762050593046014);

    float ss = 0.f;
    for (int j = threadIdx.x; j < HID_; j += 256) {
        float v = x[j];
        sh[j] = v;
        ss += v * v;
    }
#pragma unroll
    for (int o = 16; o; o >>= 1) ss += __shfl_xor_sync(0xffffffffu, ss, o);
    if ((threadIdx.x & 31) == 0) red[threadIdx.x >> 5] = ss;
    __syncthreads();
    float tot = red[0] + red[1] + red[2] + red[3] +
                red[4] + red[5] + red[6] + red[7];
    const float rstd = rsqrtf(tot * (1.0f / HID_) + EPS_);
    const float p = (float)positions[t];

    for (int j = threadIdx.x; j < HID_; j += 256) {
        const int h = j >> 7;
        const int d = j & 127;
        float out;
        if (mode == 2) {
            out = sh[j] + bias[(h << 7) + d];
        } else {
            const float y = sh[j] * rstd * (1.f + w[j]);
            const float ang = p * shInv[d & 63];
            const float c = cosf(ang);
            const float s = sinf(ang);
            const int partner = (d < 64) ? j + 64 : j - 64;
            const float y2 = sh[partner] * rstd * (1.f + w[partner]);
            out = (d < 64) ? (y * c - y2 * s) : (y * c + y2 * s);
            if (mode == 0) out *= ATTN_SCALE;
            else           out += bias[(h << 7) + d];
        }
        Xt[(((long long)(b * H_ + h)) * L_ + l) * D_ + d] = out;
    }
}

// ---------------------------------------------------------------------------
// scores = softcap(Q@K^T) + mask   (fp32, mask 4-byte nonzero == keep)
// ---------------------------------------------------------------------------
__global__ __launch_bounds__(256, 2) void scores_kernel(
    const float* __restrict__ Qt, const float* __restrict__ Kt,
    const unsigned int* __restrict__ mask, float* __restrict__ S)
{
    __shared__ float As[8][128];
    __shared__ float Bs[8][128];
    const int bh = blockIdx.z;
    const int b  = bh >> 4;
    const int tid  = threadIdx.x;
    const int m0   = blockIdx.y * 128;
    const int n0   = blockIdx.x * 128;
    const int lrow = tid >> 1;
    const int lcol = (tid & 1) * 4;
    const int ty   = tid >> 4;
    const int tx   = tid & 15;
    const float* Ap = Qt + (long long)bh * L_ * D_ + (long long)(m0 + lrow) * D_ + lcol;
    const float* Bp = Kt + (long long)bh * L_ * D_ + (long long)(n0 + lrow) * D_ + lcol;

    float acc[8][8] = {};
    for (int k0 = 0; k0 < D_; k0 += 8) {
        float4 av = *(const float4*)(Ap + k0);
        float4 bv = *(const float4*)(Bp + k0);
        As[lcol + 0][lrow] = av.x; As[lcol + 1][lrow] = av.y;
        As[lcol + 2][lrow] = av.z; As[lcol + 3][lrow] = av.w;
        Bs[lcol + 0][lrow] = bv.x; Bs[lcol + 1][lrow] = bv.y;
        Bs[lcol + 2][lrow] = bv.z; Bs[lcol + 3][lrow] = bv.w;
        __syncthreads();
#pragma unroll
        for (int kk = 0; kk < 8; ++kk) {
            float af[8], bf[8];
            *(float4*)(af)     = *(const float4*)(&As[kk][ty * 8]);
            *(float4*)(af + 4) = *(const float4*)(&As[kk][ty * 8 + 4]);
            *(float4*)(bf)     = *(const float4*)(&Bs[kk][tx * 8]);
            *(float4*)(bf + 4) = *(const float4*)(&Bs[kk][tx * 8 + 4]);
#pragma unroll
            for (int i = 0; i < 8; ++i)
#pragma unroll
                for (int j = 0; j < 8; ++j)
                    acc[i][j] = fmaf(af[i], bf[j], acc[i][j]);
        }
        __syncthreads();
    }
    const unsigned int* mrow = mask + (long long)b * L_ * L_;
    float* Srow = S + (long long)bh * L_ * L_;
#pragma unroll
    for (int i = 0; i < 8; ++i) {
        const int q = m0 + ty * 8 + i;
#pragma unroll
        for (int j = 0; j < 8; ++j) {
            const int kc = n0 + tx * 8 + j;
            float s = acc[i][j];
            s = SOFTCAP * tanhf(s * (1.0f / SOFTCAP));
            if (mrow[(long long)q * L_ + kc] == 0u) s = NEGF;
            Srow[(long long)q * L_ + kc] = s;
        }
    }
}

__global__ __launch_bounds__(256) void softmax_kernel(float* __restrict__ S)
{
    __shared__ float red[8];
    float* p = S + (long long)blockIdx.x * L_;
    float vals[8];
    float mx = -3.402823466e38f;
#pragma unroll
    for (int i = 0; i < 8; ++i) {
        vals[i] = p[threadIdx.x + i * 256];
        mx = fmaxf(mx, vals[i]);
    }
#pragma unroll
    for (int o = 16; o; o >>= 1) mx = fmaxf(mx, __shfl_xor_sync(0xffffffffu, mx, o));
    if ((threadIdx.x & 31) == 0) red[threadIdx.x >> 5] = mx;
    __syncthreads();
    mx = fmaxf(fmaxf(fmaxf(red[0], red[1]), fmaxf(red[2], red[3])),
               fmaxf(fmaxf(red[4], red[5]), fmaxf(red[6], red[7])));
    __syncthreads();
    float sum = 0.f;
#pragma unroll
    for (int i = 0; i < 8; ++i) {
        vals[i] = expf(vals[i] - mx);
        sum += vals[i];
    }
#pragma unroll
    for (int o = 16; o; o >>= 1) sum += __shfl_xor_sync(0xffffffffu, sum, o);
    if ((threadIdx.x & 31) == 0) red[threadIdx.x >> 5] = sum;
    __syncthreads();
    sum = red[0] + red[1] + red[2] + red[3] + red[4] + red[5] + red[6] + red[7];
    const float inv = 1.0f / sum;
#pragma unroll
    for (int i = 0; i < 8; ++i) p[threadIdx.x + i * 256] = vals[i] * inv;
}

__global__ __launch_bounds__(256, 2) void pv_kernel(
    const float* __restrict__ S, const float* __restrict__ Vt,
    float* __restrict__ O)
{
    __shared__ float As[8][128];
    __shared__ float Bs[8][128];
    const int bh = blockIdx.y;
    const int b = bh >> 4, h = bh & 15;
    const int tid  = threadIdx.x;
    const int m0   = blockIdx.x * 128;
    const int lrow = tid >> 1;
    const int lcol = (tid & 1) * 4;
    const int brow = tid >> 5;
    const int bcol = (tid & 31) * 4;
    const int ty   = tid >> 4;
    const int tx   = tid & 15;
    const float* Ap = S + (long long)bh * L_ * L_ + (long long)(m0 + lrow) * L_ + lcol;
    const float* Bp = Vt + (long long)bh * L_ * D_;

    float acc[8][8] = {};
    for (int k0 = 0; k0 < L_; k0 += 8) {
        float4 av = *(const float4*)(Ap + k0);
        As[lcol + 0][lrow] = av.x; As[lcol + 1][lrow] = av.y;
        As[lcol + 2][lrow] = av.z; As[lcol + 3][lrow] = av.w;
        float4 bv = *(const float4*)(Bp + (long long)(k0 + brow) * D_ + bcol);
        *(float4*)&Bs[brow][bcol] = bv;
        __syncthreads();
#pragma unroll
        for (int kk = 0; kk < 8; ++kk) {
            float af[8], bf[8];
            *(float4*)(af)     = *(const float4*)(&As[kk][ty * 8]);
            *(float4*)(af + 4) = *(const float4*)(&As[kk][ty * 8 + 4]);
            *(float4*)(bf)     = *(const float4*)(&Bs[kk][tx * 8]);
            *(float4*)(bf + 4) = *(const float4*)(&Bs[kk][tx * 8 + 4]);
#pragma unroll
            for (int i = 0; i < 8; ++i)
#pragma unroll
                for (int j = 0; j < 8; ++j)
                    acc[i][j] = fmaf(af[i], bf[j], acc[i][j]);
        }
        __syncthreads();
    }
#pragma unroll
    for (int i = 0; i < 8; ++i) {
        const int m = m0 + ty * 8 + i;
        float* cp = O + ((long long)(b * L_ + m) * H_ + h) * D_ + tx * 8;
        *(float4*)cp       = make_float4(acc[i][0], acc[i][1], acc[i][2], acc[i][3]);
        *(float4*)(cp + 4) = make_float4(acc[i][4], acc[i][5], acc[i][6], acc[i][7]);
    }
}

// ---------------------------------------------------------------------------
static float* sym_addr(const void* sym)
{
    void* p = nullptr;
    cudaGetSymbolAddress(&p, sym);
    return (float*)p;
}

extern "C" void kernel_launch(void* const* d_in, const int* in_sizes, int n_in,
                              void* d_out, int out_size)
{
    (void)in_sizes; (void)n_in; (void)out_size;
    const float* hs = (const float*)d_in[0];
    const float* Wq = (const float*)d_in[1];
    const float* Wk = (const float*)d_in[2];
    const float* Wv = (const float*)d_in[3];
    const float* Wo = (const float*)d_in[4];
    const float* qw = (const float*)d_in[5];
    const float* kw = (const float*)d_in[6];
    const float* kb = (const float*)d_in[7];
    const float* vb = (const float*)d_in[8];
    const int*   pos  = (const int*)d_in[9];
    const unsigned int* mask = (const unsigned int*)d_in[10];
    float* out = (float*)d_out;

    float* q    = sym_addr(g_q);
    float* k    = sym_addr(g_k);
    float* v    = sym_addr(g_v);
    float* qt   = sym_addr(g_qt);
    float* kt   = sym_addr(g_kt);
    float* vt   = sym_addr(g_vt);
    float* attn = sym_addr(g_attn);
    float* sc   = sym_addr(g_scores);
    __nv_bfloat16* ahi = (__nv_bfloat16*)sym_addr(g_ahi);
    __nv_bfloat16* alo = (__nv_bfloat16*)sym_addr(g_alo);
    __nv_bfloat16* whi = (__nv_bfloat16*)sym_addr(g_whi);
    __nv_bfloat16* wlo = (__nv_bfloat16*)sym_addr(g_wlo);

    cudaFuncSetAttribute(mma_gemm_nt,
                         cudaFuncAttributeMaxDynamicSharedMemorySize, GEMM_SMEM);

    const int nA4 = NT_ * HID_ / 4;
    const int nW4 = HID_ * HID_ / 4;
    dim3 gGemm(HID_ / 128, NT_ / 128);  // 16 x 32

    cvt_split<<<nA4 / 256, 256>>>(hs, ahi, alo, nA4);
    cvt_split<<<nW4 / 256, 256>>>(Wq, whi, wlo, nW4);
    mma_gemm_nt<<<gGemm, 256, GEMM_SMEM>>>(ahi, alo, whi, wlo, q, FAN_IN);
    cvt_split<<<nW4 / 256, 256>>>(Wk, whi, wlo, nW4);
    mma_gemm_nt<<<gGemm, 256, GEMM_SMEM>>>(ahi, alo, whi, wlo, k, FAN_IN);
    cvt_split<<<nW4 / 256, 256>>>(Wv, whi, wlo, nW4);
    mma_gemm_nt<<<gGemm, 256, GEMM_SMEM>>>(ahi, alo, whi, wlo, v, FAN_IN);

    qkv_post<<<NT_, 256>>>(q, qw, nullptr, pos, qt, 0);
    qkv_post<<<NT_, 256>>>(k, kw, kb,      pos, kt, 1);
    qkv_post<<<NT_, 256>>>(v, nullptr, vb, pos, vt, 2);

    scores_kernel<<<dim3(L_ / 128, L_ / 128, BH_), 256>>>(qt, kt, mask, sc);
    softmax_kernel<<<BH_ * L_, 256>>>(sc);
    pv_kernel<<<dim3(L_ / 128, BH_), 256>>>(sc, vt, attn);

    cvt_split<<<nA4 / 256, 256>>>(attn, ahi, alo, nA4);
    cvt_split<<<nW4 / 256, 256>>>(Wo, whi, wlo, nW4);
    mma_gemm_nt<<<gGemm, 256, GEMM_SMEM>>>(ahi, alo, whi, wlo, out, FAN_IN);
}

// round 7
// speedup vs baseline: 3.0149x; 2.6941x over previous
#include <cuda_runtime.h>
#include <cuda_bf16.h>
#include <math.h>
#include <cstdint>

// ---------------------------------------------------------------------------
// GiddAttention  B=2, L=2048, HID=2048, H=16, D=128
// Round 6: resubmit round-5 design (infra failure last round).
// Flash-fused attention on mma.sync (split-bf16 QK^T and PV),
// projections on mma.sync split-bf16. No score scratch.
// ---------------------------------------------------------------------------
namespace {
constexpr int B_   = 2;
constexpr int L_   = 2048;
constexpr int HID_ = 2048;
constexpr int H_   = 16;
constexpr int D_   = 128;
constexpr int NT_  = B_ * L_;   // 4096
constexpr int BH_  = B_ * H_;   // 32
constexpr float FAN_IN     = 0.022097086912079608f;  // 2048^-0.5
constexpr float ATTN_SCALE = 0.08838834764831845f;   // 128^-0.5
constexpr float SOFTCAP    = 30.0f;
constexpr float NEGF       = -3.402823466e38f;
constexpr float EPS_       = 1e-6f;
}

// scratch
__device__ float g_q[NT_ * HID_];
__device__ float g_k[NT_ * HID_];
__device__ float g_v[NT_ * HID_];
__device__ __nv_bfloat16 g_qthi[NT_ * HID_];  // [BH, L, D]
__device__ __nv_bfloat16 g_qtlo[NT_ * HID_];
__device__ __nv_bfloat16 g_kthi[NT_ * HID_];
__device__ __nv_bfloat16 g_ktlo[NT_ * HID_];
__device__ __nv_bfloat16 g_vthi[NT_ * HID_];
__device__ __nv_bfloat16 g_vtlo[NT_ * HID_];
__device__ __nv_bfloat16 g_ahi[NT_ * HID_];
__device__ __nv_bfloat16 g_alo[NT_ * HID_];
__device__ __nv_bfloat16 g_whi[HID_ * HID_];
__device__ __nv_bfloat16 g_wlo[HID_ * HID_];

// ------------------------------ asm helpers --------------------------------
__device__ __forceinline__ uint32_t smem_u32(const void* p) {
    uint32_t a;
    asm("{ .reg .u64 t; cvta.to.shared.u64 t, %1; cvt.u32.u64 %0, t; }"
        : "=r"(a) : "l"(p));
    return a;
}
__device__ __forceinline__ void cp_async16(uint32_t dst, const void* src) {
    asm volatile("cp.async.cg.shared.global [%0], [%1], 16;"
                 :: "r"(dst), "l"(src) : "memory");
}
__device__ __forceinline__ void cp_commit() {
    asm volatile("cp.async.commit_group;" ::: "memory");
}
template <int N>
__device__ __forceinline__ void cp_wait() {
    asm volatile("cp.async.wait_group %0;" :: "n"(N) : "memory");
}
__device__ __forceinline__ void ldsm_x4(uint32_t& r0, uint32_t& r1,
                                        uint32_t& r2, uint32_t& r3, uint32_t a) {
    asm volatile("ldmatrix.sync.aligned.m8n8.x4.shared.b16 {%0,%1,%2,%3}, [%4];"
                 : "=r"(r0), "=r"(r1), "=r"(r2), "=r"(r3) : "r"(a));
}
__device__ __forceinline__ void ldsm_x4_t(uint32_t& r0, uint32_t& r1,
                                          uint32_t& r2, uint32_t& r3, uint32_t a) {
    asm volatile("ldmatrix.sync.aligned.m8n8.x4.trans.shared.b16 {%0,%1,%2,%3}, [%4];"
                 : "=r"(r0), "=r"(r1), "=r"(r2), "=r"(r3) : "r"(a));
}
__device__ __forceinline__ void mma_bf16(float* c, const uint32_t* a,
                                         const uint32_t* b) {
    asm volatile(
        "mma.sync.aligned.m16n8k16.row.col.f32.bf16.bf16.f32 "
        "{%0,%1,%2,%3}, {%4,%5,%6,%7}, {%8,%9}, {%0,%1,%2,%3};"
        : "+f"(c[0]), "+f"(c[1]), "+f"(c[2]), "+f"(c[3])
        : "r"(a[0]), "r"(a[1]), "r"(a[2]), "r"(a[3]), "r"(b[0]), "r"(b[1]));
}
__device__ __forceinline__ uint16_t bf_bits(float x) {
    __nv_bfloat16 h = __float2bfloat16(x);
    return *(uint16_t*)&h;
}
__device__ __forceinline__ float bf_val(uint16_t u) {
    __nv_bfloat16 h = *(__nv_bfloat16*)&u;
    return __bfloat162float(h);
}
__device__ __forceinline__ void split_pack(float x, float y,
                                           uint32_t& hi, uint32_t& lo) {
    uint16_t hx = bf_bits(x), hy = bf_bits(y);
    uint16_t lx = bf_bits(x - bf_val(hx)), ly = bf_bits(y - bf_val(hy));
    hi = (uint32_t)hx | ((uint32_t)hy << 16);
    lo = (uint32_t)lx | ((uint32_t)ly << 16);
}
// swizzled offset within a tile of 256B rows; ck = 16B-chunk index (0..15)
__device__ __forceinline__ uint32_t sw256(int row, int ck) {
    return (uint32_t)(row * 256 + ((((ck & 7) ^ (row & 7)) | (ck & 8)) << 4));
}

// ---------------------------------------------------------------------------
// fp32 -> (hi, lo) bf16 split
// ---------------------------------------------------------------------------
__global__ __launch_bounds__(256) void cvt_split(
    const float* __restrict__ x, __nv_bfloat16* __restrict__ hi,
    __nv_bfloat16* __restrict__ lo, int n4)
{
    int i = blockIdx.x * 256 + threadIdx.x;
    if (i >= n4) return;
    float4 v = ((const float4*)x)[i];
    __nv_bfloat16 h[4], l[4];
    const float* f = &v.x;
#pragma unroll
    for (int j = 0; j < 4; ++j) {
        h[j] = __float2bfloat16(f[j]);
        l[j] = __float2bfloat16(f[j] - __bfloat162float(h[j]));
    }
    ((uint2*)hi)[i] = *(uint2*)h;
    ((uint2*)lo)[i] = *(uint2*)l;
}

// ---------------------------------------------------------------------------
// split-bf16 NT GEMM on mma.sync (round-4 proven)
// ---------------------------------------------------------------------------
static constexpr int GEMM_SMEM = 2 * 65536;

__global__ __launch_bounds__(256, 1) void mma_gemm_nt(
    const __nv_bfloat16* __restrict__ Ahi, const __nv_bfloat16* __restrict__ Alo,
    const __nv_bfloat16* __restrict__ Bhi, const __nv_bfloat16* __restrict__ Blo,
    float* __restrict__ C, float alpha)
{
    extern __shared__ char smem[];
    const uint32_t sb = smem_u32(smem);
    const int tid = threadIdx.x;
    const int wid = tid >> 5, lid = tid & 31;
    const int wy = wid & 1, wx = wid >> 1;
    const int m0 = blockIdx.y * 128, n0 = blockIdx.x * 128;
    const int K = 2048, N = 2048;

    const int lr8 = lid & 7, sub = lid >> 3;
    const int a_row = wy * 64 + (sub & 1) * 8 + lr8;
    const int a_col = (sub >> 1) * 8;
    const int b_row = wx * 32 + (sub >> 1) * 8 + lr8;
    const int b_col = (sub & 1) * 8;

    float acc[4][4][4] = {};

    auto load_chunk = [&](int c) {
        const uint32_t base = sb + (c & 1) * 65536;
        const int k0 = c * 64;
#pragma unroll
        for (int v = 0; v < 4; ++v) {
            const int u = v * 256 + tid;
            const int row = u >> 3, c16 = u & 7;
            const uint32_t dst = base + row * 128 + (((c16 ^ (row & 7)) << 4));
            const long long ga = (long long)(m0 + row) * K + k0 + c16 * 8;
            const long long gb = (long long)(n0 + row) * K + k0 + c16 * 8;
            cp_async16(dst,          Ahi + ga);
            cp_async16(dst + 16384,  Alo + ga);
            cp_async16(dst + 32768,  Bhi + gb);
            cp_async16(dst + 49152,  Blo + gb);
        }
        cp_commit();
    };

    auto tile_addr = [](uint32_t base, int row, int col_bf16) -> uint32_t {
        return base + row * 128 + ((((col_bf16 >> 3) ^ (row & 7)) << 4));
    };

    load_chunk(0);
    for (int c = 0; c < 32; ++c) {
        if (c < 31) {
            load_chunk(c + 1);
            cp_wait<1>();
        } else {
            cp_wait<0>();
        }
        __syncthreads();
        const uint32_t sA = sb + (c & 1) * 65536;
        const uint32_t sB = sA + 32768;
#pragma unroll
        for (int ks = 0; ks < 4; ++ks) {
            uint32_t af[2][4][4], bf[2][4][2];
#pragma unroll
            for (int i = 0; i < 4; ++i) {
                ldsm_x4(af[0][i][0], af[0][i][1], af[0][i][2], af[0][i][3],
                        tile_addr(sA,         a_row + i * 16, a_col + ks * 16));
                ldsm_x4(af[1][i][0], af[1][i][1], af[1][i][2], af[1][i][3],
                        tile_addr(sA + 16384, a_row + i * 16, a_col + ks * 16));
            }
#pragma unroll
            for (int jj = 0; jj < 2; ++jj) {
                uint32_t r0, r1, r2, r3;
                ldsm_x4(r0, r1, r2, r3,
                        tile_addr(sB,         b_row + jj * 16, b_col + ks * 16));
                bf[0][jj * 2][0] = r0; bf[0][jj * 2][1] = r1;
                bf[0][jj * 2 + 1][0] = r2; bf[0][jj * 2 + 1][1] = r3;
                ldsm_x4(r0, r1, r2, r3,
                        tile_addr(sB + 16384, b_row + jj * 16, b_col + ks * 16));
                bf[1][jj * 2][0] = r0; bf[1][jj * 2][1] = r1;
                bf[1][jj * 2 + 1][0] = r2; bf[1][jj * 2 + 1][1] = r3;
            }
#pragma unroll
            for (int i = 0; i < 4; ++i)
#pragma unroll
                for (int j = 0; j < 4; ++j)
                    mma_bf16(acc[i][j], af[0][i], bf[0][j]);
#pragma unroll
            for (int i = 0; i < 4; ++i)
#pragma unroll
                for (int j = 0; j < 4; ++j)
                    mma_bf16(acc[i][j], af[0][i], bf[1][j]);
#pragma unroll
            for (int i = 0; i < 4; ++i)
#pragma unroll
                for (int j = 0; j < 4; ++j)
                    mma_bf16(acc[i][j], af[1][i], bf[0][j]);
        }
        __syncthreads();
    }

    const int g = lid >> 2, t = lid & 3;
#pragma unroll
    for (int i = 0; i < 4; ++i) {
        const int row = m0 + wy * 64 + i * 16 + g;
#pragma unroll
        for (int j = 0; j < 4; ++j) {
            const int col = n0 + wx * 32 + j * 8 + t * 2;
            float2 v0 = make_float2(alpha * acc[i][j][0], alpha * acc[i][j][1]);
            float2 v1 = make_float2(alpha * acc[i][j][2], alpha * acc[i][j][3]);
            *(float2*)(C + (long long)row * N + col)       = v0;
            *(float2*)(C + (long long)(row + 8) * N + col) = v1;
        }
    }
}

// ---------------------------------------------------------------------------
// Per-token post: RMSNorm + RoPE + bias -> bf16 hi/lo at [BH, L, D].
// ---------------------------------------------------------------------------
__global__ __launch_bounds__(256) void qkv_post(
    const float* __restrict__ X, const float* __restrict__ w,
    const float* __restrict__ bias, const int* __restrict__ positions,
    __nv_bfloat16* __restrict__ Xhi, __nv_bfloat16* __restrict__ Xlo, int mode)
{
    __shared__ float sh[HID_];
    __shared__ float red[8];
    __shared__ float shInv[64];

    const int t = blockIdx.x;
    const int b = t >> 11;
    const int l = t & (L_ - 1);
    const float* x = X + (long long)t * HID_;

    if (threadIdx.x < 64)
        shInv[threadIdx.x] =
            (float)exp2(-(double)threadIdx.x * 0.20762050593046014);

    float ss = 0.f;
    for (int j = threadIdx.x; j < HID_; j += 256) {
        float v = x[j];
        sh[j] = v;
        ss += v * v;
    }
#pragma unroll
    for (int o = 16; o; o >>= 1) ss += __shfl_xor_sync(0xffffffffu, ss, o);
    if ((threadIdx.x & 31) == 0) red[threadIdx.x >> 5] = ss;
    __syncthreads();
    float tot = red[0] + red[1] + red[2] + red[3] +
                red[4] + red[5] + red[6] + red[7];
    const float rstd = rsqrtf(tot * (1.0f / HID_) + EPS_);
    const float p = (float)positions[t];

    for (int j = threadIdx.x; j < HID_; j += 256) {
        const int h = j >> 7;
        const int d = j & 127;
        float out;
        if (mode == 2) {
            out = sh[j] + bias[(h << 7) + d];
        } else {
            const float y = sh[j] * rstd * (1.f + w[j]);
            const float ang = p * shInv[d & 63];
            const float c = cosf(ang);
            const float s = sinf(ang);
            const int partner = (d < 64) ? j + 64 : j - 64;
            const float y2 = sh[partner] * rstd * (1.f + w[partner]);
            out = (d < 64) ? (y * c - y2 * s) : (y * c + y2 * s);
            if (mode == 0) out *= ATTN_SCALE;
            else           out += bias[(h << 7) + d];
        }
        const long long oi = (((long long)(b * H_ + h)) * L_ + l) * D_ + d;
        __nv_bfloat16 hi = __float2bfloat16(out);
        Xhi[oi] = hi;
        Xlo[oi] = __float2bfloat16(out - __bfloat162float(hi));
    }
}

// ---------------------------------------------------------------------------
// Flash attention: grid (L/128, BH), 256 threads (8 warps x 16 q-rows).
// ---------------------------------------------------------------------------
static constexpr int FLASH_SMEM = 196608;

__global__ __launch_bounds__(256, 1) void flash_attn(
    const __nv_bfloat16* __restrict__ Qhi, const __nv_bfloat16* __restrict__ Qlo,
    const __nv_bfloat16* __restrict__ Khi, const __nv_bfloat16* __restrict__ Klo,
    const __nv_bfloat16* __restrict__ Vhi, const __nv_bfloat16* __restrict__ Vlo,
    const unsigned int* __restrict__ mask,
    __nv_bfloat16* __restrict__ Ohi, __nv_bfloat16* __restrict__ Olo)
{
    extern __shared__ char smem[];
    const uint32_t sb = smem_u32(smem);
    const int tid = threadIdx.x, wid = tid >> 5, lid = tid & 31;
    const int bh = blockIdx.y, b = bh >> 4, h = bh & 15;
    const int q0 = blockIdx.x * 128;

    const long long qoff = ((long long)bh * L_ + q0) * D_;
    const long long koff = (long long)bh * L_ * D_;

#pragma unroll
    for (int v = 0; v < 8; ++v) {
        const int idx = v * 256 + tid;
        const int row = idx >> 4, ck = idx & 15;
        const uint32_t off = sw256(row, ck);
        cp_async16(sb + off,          Qhi + qoff + row * D_ + ck * 8);
        cp_async16(sb + 32768 + off,  Qlo + qoff + row * D_ + ck * 8);
    }
    auto load_kv = [&](int kt) {
        const uint32_t bk = 65536 + (kt & 1) * 32768;
        const uint32_t bv = 131072 + (kt & 1) * 32768;
#pragma unroll
        for (int v = 0; v < 4; ++v) {
            const int idx = v * 256 + tid;
            const int row = idx >> 4, ck = idx & 15;
            const uint32_t off = sw256(row, ck);
            const long long gg = koff + (long long)(kt * 64 + row) * D_ + ck * 8;
            cp_async16(sb + bk + off,          Khi + gg);
            cp_async16(sb + bk + 16384 + off,  Klo + gg);
            cp_async16(sb + bv + off,          Vhi + gg);
            cp_async16(sb + bv + 16384 + off,  Vlo + gg);
        }
        cp_commit();
    };
    load_kv(0);
    load_kv(1);

    cp_wait<1>();
    __syncthreads();

    const int g = lid >> 2, t4 = lid & 3;
    const int lr = lid & 15, lc = lid >> 4;

    uint32_t qh[8][4], ql[8][4];
    {
        const int row = wid * 16 + lr;
#pragma unroll
        for (int kc = 0; kc < 8; ++kc) {
            const uint32_t a = sb + sw256(row, kc * 2 + lc);
            ldsm_x4(qh[kc][0], qh[kc][1], qh[kc][2], qh[kc][3], a);
            ldsm_x4(ql[kc][0], ql[kc][1], ql[kc][2], ql[kc][3], a + 32768);
        }
    }

    float oacc[16][4];
#pragma unroll
    for (int j = 0; j < 16; ++j)
        oacc[j][0] = oacc[j][1] = oacc[j][2] = oacc[j][3] = 0.f;
    float m0 = NEGF, m1 = NEGF, l0 = 0.f, l1 = 0.f;

    const int r0 = q0 + wid * 16 + g;
    const unsigned int* mrow0 = mask + (long long)b * L_ * L_ + (long long)r0 * L_;
    const unsigned int* mrow1 = mrow0 + 8 * L_;

    for (int kt = 0; kt < 32; ++kt) {
        if (kt == 31) cp_wait<0>(); else cp_wait<1>();
        __syncthreads();
        const uint32_t bk = sb + 65536 + (kt & 1) * 32768;
        const uint32_t bv = sb + 131072 + (kt & 1) * 32768;

        // ---- S = Q @ K^T (3 split passes) ----
        float sacc[8][4];
#pragma unroll
        for (int j = 0; j < 8; ++j)
            sacc[j][0] = sacc[j][1] = sacc[j][2] = sacc[j][3] = 0.f;

#pragma unroll
        for (int kc = 0; kc < 8; ++kc) {
            const int ck = kc * 2 + lc;
#pragma unroll
            for (int jj = 0; jj < 4; ++jj) {
                const int row = jj * 16 + lr;
                const uint32_t a = bk + sw256(row, ck);
                uint32_t h0, h1, h2, h3, e0, e1, e2, e3;
                ldsm_x4(h0, h1, h2, h3, a);
                ldsm_x4(e0, e1, e2, e3, a + 16384);
                uint32_t bb[2];
                bb[0] = h0; bb[1] = h2;
                mma_bf16(sacc[2 * jj], qh[kc], bb);
                mma_bf16(sacc[2 * jj], ql[kc], bb);
                bb[0] = e0; bb[1] = e2;
                mma_bf16(sacc[2 * jj], qh[kc], bb);
                bb[0] = h1; bb[1] = h3;
                mma_bf16(sacc[2 * jj + 1], qh[kc], bb);
                mma_bf16(sacc[2 * jj + 1], ql[kc], bb);
                bb[0] = e1; bb[1] = e3;
                mma_bf16(sacc[2 * jj + 1], qh[kc], bb);
            }
        }

        // ---- softcap + mask ----
        const int kb = kt * 64;
#pragma unroll
        for (int j = 0; j < 8; ++j) {
            const int kc2 = kb + j * 8 + 2 * t4;
            const uint2 ma = *(const uint2*)(mrow0 + kc2);
            const uint2 mb = *(const uint2*)(mrow1 + kc2);
#pragma unroll
            for (int e = 0; e < 4; ++e) {
                float s = sacc[j][e];
                const float tt = __expf(s * (2.0f / SOFTCAP));
                s = SOFTCAP * __fdividef(tt - 1.0f, tt + 1.0f);
                const unsigned int mm = (e == 0) ? ma.x : (e == 1) ? ma.y
                                        : (e == 2) ? mb.x : mb.y;
                sacc[j][e] = (mm != 0u) ? s : NEGF;
            }
        }

        // ---- online softmax ----
        float rx0 = NEGF, rx1 = NEGF;
#pragma unroll
        for (int j = 0; j < 8; ++j) {
            rx0 = fmaxf(rx0, fmaxf(sacc[j][0], sacc[j][1]));
            rx1 = fmaxf(rx1, fmaxf(sacc[j][2], sacc[j][3]));
        }
        rx0 = fmaxf(rx0, __shfl_xor_sync(0xffffffffu, rx0, 1));
        rx0 = fmaxf(rx0, __shfl_xor_sync(0xffffffffu, rx0, 2));
        rx1 = fmaxf(rx1, __shfl_xor_sync(0xffffffffu, rx1, 1));
        rx1 = fmaxf(rx1, __shfl_xor_sync(0xffffffffu, rx1, 2));
        const float nm0 = fmaxf(m0, rx0), nm1 = fmaxf(m1, rx1);
        const float sc0 = __expf(m0 - nm0), sc1 = __expf(m1 - nm1);
        m0 = nm0; m1 = nm1;
        float ps0 = 0.f, ps1 = 0.f;
#pragma unroll
        for (int j = 0; j < 8; ++j) {
            sacc[j][0] = __expf(sacc[j][0] - nm0);
            sacc[j][1] = __expf(sacc[j][1] - nm0);
            sacc[j][2] = __expf(sacc[j][2] - nm1);
            sacc[j][3] = __expf(sacc[j][3] - nm1);
            ps0 += sacc[j][0] + sacc[j][1];
            ps1 += sacc[j][2] + sacc[j][3];
        }
        l0 = l0 * sc0 + ps0;
        l1 = l1 * sc1 + ps1;
#pragma unroll
        for (int j = 0; j < 16; ++j) {
            oacc[j][0] *= sc0; oacc[j][1] *= sc0;
            oacc[j][2] *= sc1; oacc[j][3] *= sc1;
        }

        // ---- P fragments (hi/lo) ----
        uint32_t ph[4][4], pl[4][4];
#pragma unroll
        for (int c2 = 0; c2 < 4; ++c2) {
            split_pack(sacc[2 * c2][0],     sacc[2 * c2][1],     ph[c2][0], pl[c2][0]);
            split_pack(sacc[2 * c2][2],     sacc[2 * c2][3],     ph[c2][1], pl[c2][1]);
            split_pack(sacc[2 * c2 + 1][0], sacc[2 * c2 + 1][1], ph[c2][2], pl[c2][2]);
            split_pack(sacc[2 * c2 + 1][2], sacc[2 * c2 + 1][3], ph[c2][3], pl[c2][3]);
        }

        // ---- O += P @ V (3 split passes, V via ldsm.trans) ----
#pragma unroll
        for (int c2 = 0; c2 < 4; ++c2) {
            const int krow = c2 * 16 + lr;
#pragma unroll
            for (int jj = 0; jj < 8; ++jj) {
                const uint32_t a = bv + sw256(krow, jj * 2 + lc);
                uint32_t h0, h1, h2, h3, e0, e1, e2, e3;
                ldsm_x4_t(h0, h1, h2, h3, a);
                ldsm_x4_t(e0, e1, e2, e3, a + 16384);
                uint32_t bb[2];
                bb[0] = h0; bb[1] = h1;
                mma_bf16(oacc[2 * jj], ph[c2], bb);
                mma_bf16(oacc[2 * jj], pl[c2], bb);
                bb[0] = e0; bb[1] = e1;
                mma_bf16(oacc[2 * jj], ph[c2], bb);
                bb[0] = h2; bb[1] = h3;
                mma_bf16(oacc[2 * jj + 1], ph[c2], bb);
                mma_bf16(oacc[2 * jj + 1], pl[c2], bb);
                bb[0] = e2; bb[1] = e3;
                mma_bf16(oacc[2 * jj + 1], ph[c2], bb);
            }
        }

        __syncthreads();
        if (kt + 2 < 32) load_kv(kt + 2);
    }

    // ---- epilogue ----
    l0 += __shfl_xor_sync(0xffffffffu, l0, 1);
    l0 += __shfl_xor_sync(0xffffffffu, l0, 2);
    l1 += __shfl_xor_sync(0xffffffffu, l1, 1);
    l1 += __shfl_xor_sync(0xffffffffu, l1, 2);
    const float i0 = 1.0f / l0, i1 = 1.0f / l1;

    const long long base0 = (long long)(b * L_ + r0) * HID_ + h * D_;
    const long long base1 = base0 + 8LL * HID_;
#pragma unroll
    for (int j = 0; j < 16; ++j) {
        const int d = j * 8 + 2 * t4;
        uint32_t hi0, lo0, hi1, lo1;
        split_pack(oacc[j][0] * i0, oacc[j][1] * i0, hi0, lo0);
        split_pack(oacc[j][2] * i1, oacc[j][3] * i1, hi1, lo1);
        *(uint32_t*)(Ohi + base0 + d) = hi0;
        *(uint32_t*)(Olo + base0 + d) = lo0;
        *(uint32_t*)(Ohi + base1 + d) = hi1;
        *(uint32_t*)(Olo + base1 + d) = lo1;
    }
}

// ---------------------------------------------------------------------------
static float* sym_addr(const void* sym)
{
    void* p = nullptr;
    cudaGetSymbolAddress(&p, sym);
    return (float*)p;
}

extern "C" void kernel_launch(void* const* d_in, const int* in_sizes, int n_in,
                              void* d_out, int out_size)
{
    (void)in_sizes; (void)n_in; (void)out_size;
    const float* hs = (const float*)d_in[0];
    const float* Wq = (const float*)d_in[1];
    const float* Wk = (const float*)d_in[2];
    const float* Wv = (const float*)d_in[3];
    const float* Wo = (const float*)d_in[4];
    const float* qw = (const float*)d_in[5];
    const float* kw = (const float*)d_in[6];
    const float* kb = (const float*)d_in[7];
    const float* vb = (const float*)d_in[8];
    const int*   pos  = (const int*)d_in[9];
    const unsigned int* mask = (const unsigned int*)d_in[10];
    float* out = (float*)d_out;

    float* q = sym_addr(g_q);
    float* k = sym_addr(g_k);
    float* v = sym_addr(g_v);
    __nv_bfloat16* qthi = (__nv_bfloat16*)sym_addr(g_qthi);
    __nv_bfloat16* qtlo = (__nv_bfloat16*)sym_addr(g_qtlo);
    __nv_bfloat16* kthi = (__nv_bfloat16*)sym_addr(g_kthi);
    __nv_bfloat16* ktlo = (__nv_bfloat16*)sym_addr(g_ktlo);
    __nv_bfloat16* vthi = (__nv_bfloat16*)sym_addr(g_vthi);
    __nv_bfloat16* vtlo = (__nv_bfloat16*)sym_addr(g_vtlo);
    __nv_bfloat16* ahi  = (__nv_bfloat16*)sym_addr(g_ahi);
    __nv_bfloat16* alo  = (__nv_bfloat16*)sym_addr(g_alo);
    __nv_bfloat16* whi  = (__nv_bfloat16*)sym_addr(g_whi);
    __nv_bfloat16* wlo  = (__nv_bfloat16*)sym_addr(g_wlo);

    cudaFuncSetAttribute(mma_gemm_nt,
                         cudaFuncAttributeMaxDynamicSharedMemorySize, GEMM_SMEM);
    cudaFuncSetAttribute(flash_attn,
                         cudaFuncAttributeMaxDynamicSharedMemorySize, FLASH_SMEM);

    const int nA4 = NT_ * HID_ / 4;
    const int nW4 = HID_ * HID_ / 4;
    dim3 gGemm(HID_ / 128, NT_ / 128);

    cvt_split<<<nA4 / 256, 256>>>(hs, ahi, alo, nA4);
    cvt_split<<<nW4 / 256, 256>>>(Wq, whi, wlo, nW4);
    mma_gemm_nt<<<gGemm, 256, GEMM_SMEM>>>(ahi, alo, whi, wlo, q, FAN_IN);
    cvt_split<<<nW4 / 256, 256>>>(Wk, whi, wlo, nW4);
    mma_gemm_nt<<<gGemm, 256, GEMM_SMEM>>>(ahi, alo, whi, wlo, k, FAN_IN);
    cvt_split<<<nW4 / 256, 256>>>(Wv, whi, wlo, nW4);
    mma_gemm_nt<<<gGemm, 256, GEMM_SMEM>>>(ahi, alo, whi, wlo, v, FAN_IN);

    qkv_post<<<NT_, 256>>>(q, qw, nullptr, pos, qthi, qtlo, 0);
    qkv_post<<<NT_, 256>>>(k, kw, kb,      pos, kthi, ktlo, 1);
    qkv_post<<<NT_, 256>>>(v, nullptr, vb, pos, vthi, vtlo, 2);

    flash_attn<<<dim3(L_ / 128, BH_), 256, FLASH_SMEM>>>(
        qthi, qtlo, kthi, ktlo, vthi, vtlo, mask, ahi, alo);

    cvt_split<<<nW4 / 256, 256>>>(Wo, whi, wlo, nW4);
    mma_gemm_nt<<<gGemm, 256, GEMM_SMEM>>>(ahi, alo, whi, wlo, out, FAN_IN);
}

// round 8
// speedup vs baseline: 3.1432x; 1.0426x over previous
#include <cuda_runtime.h>
#include <cuda_bf16.h>
#include <math.h>
#include <cstdint>

// ---------------------------------------------------------------------------
// GiddAttention  B=2, L=2048, HID=2048, H=16, D=128
// Round 8: fused QKV GEMM (N=6144) with 128x256 CTA tile / 64x64 warp tile,
// fused qkv_post, flash attention unchanged from round 7.
// ---------------------------------------------------------------------------
namespace {
constexpr int B_   = 2;
constexpr int L_   = 2048;
constexpr int HID_ = 2048;
constexpr int H_   = 16;
constexpr int D_   = 128;
constexpr int NT_  = B_ * L_;   // 4096
constexpr int BH_  = B_ * H_;   // 32
constexpr float FAN_IN     = 0.022097086912079608f;  // 2048^-0.5
constexpr float ATTN_SCALE = 0.08838834764831845f;   // 128^-0.5
constexpr float SOFTCAP    = 30.0f;
constexpr float NEGF       = -3.402823466e38f;
constexpr float EPS_       = 1e-6f;
}

// scratch
__device__ float g_qkv[(size_t)NT_ * 3 * HID_];          // packed q|k|v, 100MB
__device__ __nv_bfloat16 g_qthi[NT_ * HID_];  // [BH, L, D]
__device__ __nv_bfloat16 g_qtlo[NT_ * HID_];
__device__ __nv_bfloat16 g_kthi[NT_ * HID_];
__device__ __nv_bfloat16 g_ktlo[NT_ * HID_];
__device__ __nv_bfloat16 g_vthi[NT_ * HID_];
__device__ __nv_bfloat16 g_vtlo[NT_ * HID_];
__device__ __nv_bfloat16 g_ahi[NT_ * HID_];
__device__ __nv_bfloat16 g_alo[NT_ * HID_];
__device__ __nv_bfloat16 g_whi[3 * HID_ * HID_];
__device__ __nv_bfloat16 g_wlo[3 * HID_ * HID_];

// ------------------------------ asm helpers --------------------------------
__device__ __forceinline__ uint32_t smem_u32(const void* p) {
    uint32_t a;
    asm("{ .reg .u64 t; cvta.to.shared.u64 t, %1; cvt.u32.u64 %0, t; }"
        : "=r"(a) : "l"(p));
    return a;
}
__device__ __forceinline__ void cp_async16(uint32_t dst, const void* src) {
    asm volatile("cp.async.cg.shared.global [%0], [%1], 16;"
                 :: "r"(dst), "l"(src) : "memory");
}
__device__ __forceinline__ void cp_commit() {
    asm volatile("cp.async.commit_group;" ::: "memory");
}
template <int N>
__device__ __forceinline__ void cp_wait() {
    asm volatile("cp.async.wait_group %0;" :: "n"(N) : "memory");
}
__device__ __forceinline__ void ldsm_x4(uint32_t& r0, uint32_t& r1,
                                        uint32_t& r2, uint32_t& r3, uint32_t a) {
    asm volatile("ldmatrix.sync.aligned.m8n8.x4.shared.b16 {%0,%1,%2,%3}, [%4];"
                 : "=r"(r0), "=r"(r1), "=r"(r2), "=r"(r3) : "r"(a));
}
__device__ __forceinline__ void ldsm_x4_t(uint32_t& r0, uint32_t& r1,
                                          uint32_t& r2, uint32_t& r3, uint32_t a) {
    asm volatile("ldmatrix.sync.aligned.m8n8.x4.trans.shared.b16 {%0,%1,%2,%3}, [%4];"
                 : "=r"(r0), "=r"(r1), "=r"(r2), "=r"(r3) : "r"(a));
}
__device__ __forceinline__ void mma_bf16(float* c, const uint32_t* a,
                                         const uint32_t* b) {
    asm volatile(
        "mma.sync.aligned.m16n8k16.row.col.f32.bf16.bf16.f32 "
        "{%0,%1,%2,%3}, {%4,%5,%6,%7}, {%8,%9}, {%0,%1,%2,%3};"
        : "+f"(c[0]), "+f"(c[1]), "+f"(c[2]), "+f"(c[3])
        : "r"(a[0]), "r"(a[1]), "r"(a[2]), "r"(a[3]), "r"(b[0]), "r"(b[1]));
}
__device__ __forceinline__ uint16_t bf_bits(float x) {
    __nv_bfloat16 h = __float2bfloat16(x);
    return *(uint16_t*)&h;
}
__device__ __forceinline__ float bf_val(uint16_t u) {
    __nv_bfloat16 h = *(__nv_bfloat16*)&u;
    return __bfloat162float(h);
}
__device__ __forceinline__ void split_pack(float x, float y,
                                           uint32_t& hi, uint32_t& lo) {
    uint16_t hx = bf_bits(x), hy = bf_bits(y);
    uint16_t lx = bf_bits(x - bf_val(hx)), ly = bf_bits(y - bf_val(hy));
    hi = (uint32_t)hx | ((uint32_t)hy << 16);
    lo = (uint32_t)lx | ((uint32_t)ly << 16);
}
// swizzled offset: 128B rows (col chunks of 16B)
__device__ __forceinline__ uint32_t sw128o(int row, int ck) {
    return (uint32_t)(row * 128 + (((ck ^ (row & 7)) << 4)));
}
// swizzled offset within a tile of 256B rows; ck = 16B-chunk index (0..15)
__device__ __forceinline__ uint32_t sw256(int row, int ck) {
    return (uint32_t)(row * 256 + ((((ck & 7) ^ (row & 7)) | (ck & 8)) << 4));
}

// ---------------------------------------------------------------------------
// fp32 -> (hi, lo) bf16 split
// ---------------------------------------------------------------------------
__global__ __launch_bounds__(256) void cvt_split(
    const float* __restrict__ x, __nv_bfloat16* __restrict__ hi,
    __nv_bfloat16* __restrict__ lo, int n4)
{
    int i = blockIdx.x * 256 + threadIdx.x;
    if (i >= n4) return;
    float4 v = ((const float4*)x)[i];
    __nv_bfloat16 h[4], l[4];
    const float* f = &v.x;
#pragma unroll
    for (int j = 0; j < 4; ++j) {
        h[j] = __float2bfloat16(f[j]);
        l[j] = __float2bfloat16(f[j] - __bfloat162float(h[j]));
    }
    ((uint2*)hi)[i] = *(uint2*)h;
    ((uint2*)lo)[i] = *(uint2*)l;
}

// ---------------------------------------------------------------------------
// split-bf16 NT GEMM: C[M,N] = alpha * (Ahi+Alo)[M,2048] @ (Bhi+Blo)[N,2048]^T
// CTA tile 128x256, warp tile 64x64 (8 warps: wy in {0,1}, wx in {0..3}).
// SMEM/buffer: Ahi 16K | Alo 16K | Bhi 32K | Blo 32K = 96K; x2 buffers.
// grid = (N/256, M/128).
// ---------------------------------------------------------------------------
static constexpr int GEMM_SMEM = 2 * 98304;

__global__ __launch_bounds__(256, 1) void mma_gemm_nt(
    const __nv_bfloat16* __restrict__ Ahi, const __nv_bfloat16* __restrict__ Alo,
    const __nv_bfloat16* __restrict__ Bhi, const __nv_bfloat16* __restrict__ Blo,
    float* __restrict__ C, float alpha, int N)
{
    extern __shared__ char smem[];
    const uint32_t sb = smem_u32(smem);
    const int tid = threadIdx.x;
    const int wid = tid >> 5, lid = tid & 31;
    const int wy = wid & 1, wx = wid >> 1;      // warp tile (wy*64, wx*64)
    const int m0 = blockIdx.y * 128, n0 = blockIdx.x * 256;
    const int K = 2048;

    const int lr8 = lid & 7, sub = lid >> 3;
    const int a_row = wy * 64 + (sub & 1) * 8 + lr8;
    const int a_col = (sub >> 1) * 8;
    const int b_row = wx * 64 + (sub >> 1) * 8 + lr8;
    const int b_col = (sub & 1) * 8;

    float acc[4][8][4] = {};

    auto load_chunk = [&](int c) {
        const uint32_t base = sb + (c & 1) * 98304;
        const int k0 = c * 64;
        // A: 128 rows x 8 chunks = 1024 units per array
#pragma unroll
        for (int v = 0; v < 4; ++v) {
            const int u = v * 256 + tid;
            const int row = u >> 3, ck = u & 7;
            const uint32_t off = sw128o(row, ck);
            const long long ga = (long long)(m0 + row) * K + k0 + ck * 8;
            cp_async16(base + off,          Ahi + ga);
            cp_async16(base + 16384 + off,  Alo + ga);
        }
        // B: 256 rows x 8 chunks = 2048 units per array
#pragma unroll
        for (int v = 0; v < 8; ++v) {
            const int u = v * 256 + tid;
            const int row = u >> 3, ck = u & 7;
            const uint32_t off = sw128o(row, ck);
            const long long gb = (long long)(n0 + row) * K + k0 + ck * 8;
            cp_async16(base + 32768 + off,  Bhi + gb);
            cp_async16(base + 65536 + off,  Blo + gb);
        }
        cp_commit();
    };

    load_chunk(0);
    for (int c = 0; c < 32; ++c) {
        if (c < 31) {
            load_chunk(c + 1);
            cp_wait<1>();
        } else {
            cp_wait<0>();
        }
        __syncthreads();
        const uint32_t base = sb + (c & 1) * 98304;
        const uint32_t sB = base + 32768;
#pragma unroll
        for (int ks = 0; ks < 4; ++ks) {
            uint32_t af[2][4][4], bf[2][8][2];
#pragma unroll
            for (int i = 0; i < 4; ++i) {
                const int row = a_row + i * 16;
                const int ck = (a_col + ks * 16) >> 3;
                ldsm_x4(af[0][i][0], af[0][i][1], af[0][i][2], af[0][i][3],
                        base + sw128o(row, ck));
                ldsm_x4(af[1][i][0], af[1][i][1], af[1][i][2], af[1][i][3],
                        base + 16384 + sw128o(row, ck));
            }
#pragma unroll
            for (int jj = 0; jj < 4; ++jj) {
                const int row = b_row + jj * 16;
                const int ck = (b_col + ks * 16) >> 3;
                uint32_t r0, r1, r2, r3;
                ldsm_x4(r0, r1, r2, r3, sB + sw128o(row, ck));
                bf[0][jj * 2][0] = r0; bf[0][jj * 2][1] = r1;
                bf[0][jj * 2 + 1][0] = r2; bf[0][jj * 2 + 1][1] = r3;
                ldsm_x4(r0, r1, r2, r3, sB + 32768 + sw128o(row, ck));
                bf[1][jj * 2][0] = r0; bf[1][jj * 2][1] = r1;
                bf[1][jj * 2 + 1][0] = r2; bf[1][jj * 2 + 1][1] = r3;
            }
#pragma unroll
            for (int i = 0; i < 4; ++i)
#pragma unroll
                for (int j = 0; j < 8; ++j)
                    mma_bf16(acc[i][j], af[0][i], bf[0][j]);
#pragma unroll
            for (int i = 0; i < 4; ++i)
#pragma unroll
                for (int j = 0; j < 8; ++j)
                    mma_bf16(acc[i][j], af[0][i], bf[1][j]);
#pragma unroll
            for (int i = 0; i < 4; ++i)
#pragma unroll
                for (int j = 0; j < 8; ++j)
                    mma_bf16(acc[i][j], af[1][i], bf[0][j]);
        }
        __syncthreads();
    }

    const int g = lid >> 2, t = lid & 3;
#pragma unroll
    for (int i = 0; i < 4; ++i) {
        const int row = m0 + wy * 64 + i * 16 + g;
#pragma unroll
        for (int j = 0; j < 8; ++j) {
            const int col = n0 + wx * 64 + j * 8 + t * 2;
            float2 v0 = make_float2(alpha * acc[i][j][0], alpha * acc[i][j][1]);
            float2 v1 = make_float2(alpha * acc[i][j][2], alpha * acc[i][j][3]);
            *(float2*)(C + (long long)row * N + col)       = v0;
            *(float2*)(C + (long long)(row + 8) * N + col) = v1;
        }
    }
}

// ---------------------------------------------------------------------------
// Fused per-token post for q|k|v packed rows:
// RMSNorm(q,k) + RoPE(q,k) + bias(k,v) -> bf16 hi/lo at [BH, L, D].
// ---------------------------------------------------------------------------
__global__ __launch_bounds__(256) void qkv_post3(
    const float* __restrict__ QKV,
    const float* __restrict__ qw, const float* __restrict__ kw,
    const float* __restrict__ kb, const float* __restrict__ vb,
    const int* __restrict__ positions,
    __nv_bfloat16* __restrict__ Qhi, __nv_bfloat16* __restrict__ Qlo,
    __nv_bfloat16* __restrict__ Khi, __nv_bfloat16* __restrict__ Klo,
    __nv_bfloat16* __restrict__ Vhi, __nv_bfloat16* __restrict__ Vlo)
{
    __shared__ float sh[3 * HID_];
    __shared__ float redq[8], redk[8];
    __shared__ float shInv[64];

    const int t = blockIdx.x;
    const int b = t >> 11;
    const int l = t & (L_ - 1);
    const float* x = QKV + (long long)t * (3 * HID_);

    if (threadIdx.x < 64)
        shInv[threadIdx.x] =
            (float)exp2(-(double)threadIdx.x * 0.20762050593046014);

    float sq = 0.f, sk = 0.f;
    for (int j = threadIdx.x; j < 2 * HID_; j += 256) {
        float v = x[j];
        sh[j] = v;
        if (j < HID_) sq += v * v; else sk += v * v;
    }
    for (int j = 2 * HID_ + threadIdx.x; j < 3 * HID_; j += 256)
        sh[j] = x[j];
#pragma unroll
    for (int o = 16; o; o >>= 1) {
        sq += __shfl_xor_sync(0xffffffffu, sq, o);
        sk += __shfl_xor_sync(0xffffffffu, sk, o);
    }
    if ((threadIdx.x & 31) == 0) {
        redq[threadIdx.x >> 5] = sq;
        redk[threadIdx.x >> 5] = sk;
    }
    __syncthreads();
    float tq = redq[0] + redq[1] + redq[2] + redq[3] +
               redq[4] + redq[5] + redq[6] + redq[7];
    float tk = redk[0] + redk[1] + redk[2] + redk[3] +
               redk[4] + redk[5] + redk[6] + redk[7];
    const float rsq = rsqrtf(tq * (1.0f / HID_) + EPS_);
    const float rsk = rsqrtf(tk * (1.0f / HID_) + EPS_);
    const float p = (float)positions[t];

    for (int j = threadIdx.x; j < HID_; j += 256) {
        const int h = j >> 7;
        const int d = j & 127;
        const long long oi = (((long long)(b * H_ + h)) * L_ + l) * D_ + d;
        const int partner = (d < 64) ? j + 64 : j - 64;
        const float ang = p * shInv[d & 63];
        const float co = cosf(ang);
        const float si = sinf(ang);

        // q
        {
            const float y  = sh[j] * rsq * (1.f + qw[j]);
            const float y2 = sh[partner] * rsq * (1.f + qw[partner]);
            float o = ((d < 64) ? (y * co - y2 * si) : (y * co + y2 * si)) * ATTN_SCALE;
            __nv_bfloat16 hi = __float2bfloat16(o);
            Qhi[oi] = hi;
            Qlo[oi] = __float2bfloat16(o - __bfloat162float(hi));
        }
        // k
        {
            const float y  = sh[HID_ + j] * rsk * (1.f + kw[j]);
            const float y2 = sh[HID_ + partner] * rsk * (1.f + kw[partner]);
            float o = ((d < 64) ? (y * co - y2 * si) : (y * co + y2 * si))
                      + kb[(h << 7) + d];
            __nv_bfloat16 hi = __float2bfloat16(o);
            Khi[oi] = hi;
            Klo[oi] = __float2bfloat16(o - __bfloat162float(hi));
        }
        // v
        {
            float o = sh[2 * HID_ + j] + vb[(h << 7) + d];
            __nv_bfloat16 hi = __float2bfloat16(o);
            Vhi[oi] = hi;
            Vlo[oi] = __float2bfloat16(o - __bfloat162float(hi));
        }
    }
}

// ---------------------------------------------------------------------------
// Flash attention: grid (L/128, BH), 256 threads (8 warps x 16 q-rows).
// (unchanged from round 7)
// ---------------------------------------------------------------------------
static constexpr int FLASH_SMEM = 196608;

__global__ __launch_bounds__(256, 1) void flash_attn(
    const __nv_bfloat16* __restrict__ Qhi, const __nv_bfloat16* __restrict__ Qlo,
    const __nv_bfloat16* __restrict__ Khi, const __nv_bfloat16* __restrict__ Klo,
    const __nv_bfloat16* __restrict__ Vhi, const __nv_bfloat16* __restrict__ Vlo,
    const unsigned int* __restrict__ mask,
    __nv_bfloat16* __restrict__ Ohi, __nv_bfloat16* __restrict__ Olo)
{
    extern __shared__ char smem[];
    const uint32_t sb = smem_u32(smem);
    const int tid = threadIdx.x, wid = tid >> 5, lid = tid & 31;
    const int bh = blockIdx.y, b = bh >> 4, h = bh & 15;
    const int q0 = blockIdx.x * 128;

    const long long qoff = ((long long)bh * L_ + q0) * D_;
    const long long koff = (long long)bh * L_ * D_;

#pragma unroll
    for (int v = 0; v < 8; ++v) {
        const int idx = v * 256 + tid;
        const int row = idx >> 4, ck = idx & 15;
        const uint32_t off = sw256(row, ck);
        cp_async16(sb + off,          Qhi + qoff + row * D_ + ck * 8);
        cp_async16(sb + 32768 + off,  Qlo + qoff + row * D_ + ck * 8);
    }
    auto load_kv = [&](int kt) {
        const uint32_t bk = 65536 + (kt & 1) * 32768;
        const uint32_t bv = 131072 + (kt & 1) * 32768;
#pragma unroll
        for (int v = 0; v < 4; ++v) {
            const int idx = v * 256 + tid;
            const int row = idx >> 4, ck = idx & 15;
            const uint32_t off = sw256(row, ck);
            const long long gg = koff + (long long)(kt * 64 + row) * D_ + ck * 8;
            cp_async16(sb + bk + off,          Khi + gg);
            cp_async16(sb + bk + 16384 + off,  Klo + gg);
            cp_async16(sb + bv + off,          Vhi + gg);
            cp_async16(sb + bv + 16384 + off,  Vlo + gg);
        }
        cp_commit();
    };
    load_kv(0);
    load_kv(1);

    cp_wait<1>();
    __syncthreads();

    const int g = lid >> 2, t4 = lid & 3;
    const int lr = lid & 15, lc = lid >> 4;

    uint32_t qh[8][4], ql[8][4];
    {
        const int row = wid * 16 + lr;
#pragma unroll
        for (int kc = 0; kc < 8; ++kc) {
            const uint32_t a = sb + sw256(row, kc * 2 + lc);
            ldsm_x4(qh[kc][0], qh[kc][1], qh[kc][2], qh[kc][3], a);
            ldsm_x4(ql[kc][0], ql[kc][1], ql[kc][2], ql[kc][3], a + 32768);
        }
    }

    float oacc[16][4];
#pragma unroll
    for (int j = 0; j < 16; ++j)
        oacc[j][0] = oacc[j][1] = oacc[j][2] = oacc[j][3] = 0.f;
    float m0 = NEGF, m1 = NEGF, l0 = 0.f, l1 = 0.f;

    const int r0 = q0 + wid * 16 + g;
    const unsigned int* mrow0 = mask + (long long)b * L_ * L_ + (long long)r0 * L_;
    const unsigned int* mrow1 = mrow0 + 8 * L_;

    for (int kt = 0; kt < 32; ++kt) {
        if (kt == 31) cp_wait<0>(); else cp_wait<1>();
        __syncthreads();
        const uint32_t bk = sb + 65536 + (kt & 1) * 32768;
        const uint32_t bv = sb + 131072 + (kt & 1) * 32768;

        float sacc[8][4];
#pragma unroll
        for (int j = 0; j < 8; ++j)
            sacc[j][0] = sacc[j][1] = sacc[j][2] = sacc[j][3] = 0.f;

#pragma unroll
        for (int kc = 0; kc < 8; ++kc) {
            const int ck = kc * 2 + lc;
#pragma unroll
            for (int jj = 0; jj < 4; ++jj) {
                const int row = jj * 16 + lr;
                const uint32_t a = bk + sw256(row, ck);
                uint32_t h0, h1, h2, h3, e0, e1, e2, e3;
                ldsm_x4(h0, h1, h2, h3, a);
                ldsm_x4(e0, e1, e2, e3, a + 16384);
                uint32_t bb[2];
                bb[0] = h0; bb[1] = h2;
                mma_bf16(sacc[2 * jj], qh[kc], bb);
                mma_bf16(sacc[2 * jj], ql[kc], bb);
                bb[0] = e0; bb[1] = e2;
                mma_bf16(sacc[2 * jj], qh[kc], bb);
                bb[0] = h1; bb[1] = h3;
                mma_bf16(sacc[2 * jj + 1], qh[kc], bb);
                mma_bf16(sacc[2 * jj + 1], ql[kc], bb);
                bb[0] = e1; bb[1] = e3;
                mma_bf16(sacc[2 * jj + 1], qh[kc], bb);
            }
        }

        const int kb2 = kt * 64;
#pragma unroll
        for (int j = 0; j < 8; ++j) {
            const int kc2 = kb2 + j * 8 + 2 * t4;
            const uint2 ma = *(const uint2*)(mrow0 + kc2);
            const uint2 mb = *(const uint2*)(mrow1 + kc2);
#pragma unroll
            for (int e = 0; e < 4; ++e) {
                float s = sacc[j][e];
                const float tt = __expf(s * (2.0f / SOFTCAP));
                s = SOFTCAP * __fdividef(tt - 1.0f, tt + 1.0f);
                const unsigned int mm = (e == 0) ? ma.x : (e == 1) ? ma.y
                                        : (e == 2) ? mb.x : mb.y;
                sacc[j][e] = (mm != 0u) ? s : NEGF;
            }
        }

        float rx0 = NEGF, rx1 = NEGF;
#pragma unroll
        for (int j = 0; j < 8; ++j) {
            rx0 = fmaxf(rx0, fmaxf(sacc[j][0], sacc[j][1]));
            rx1 = fmaxf(rx1, fmaxf(sacc[j][2], sacc[j][3]));
        }
        rx0 = fmaxf(rx0, __shfl_xor_sync(0xffffffffu, rx0, 1));
        rx0 = fmaxf(rx0, __shfl_xor_sync(0xffffffffu, rx0, 2));
        rx1 = fmaxf(rx1, __shfl_xor_sync(0xffffffffu, rx1, 1));
        rx1 = fmaxf(rx1, __shfl_xor_sync(0xffffffffu, rx1, 2));
        const float nm0 = fmaxf(m0, rx0), nm1 = fmaxf(m1, rx1);
        const float sc0 = __expf(m0 - nm0), sc1 = __expf(m1 - nm1);
        m0 = nm0; m1 = nm1;
        float ps0 = 0.f, ps1 = 0.f;
#pragma unroll
        for (int j = 0; j < 8; ++j) {
            sacc[j][0] = __expf(sacc[j][0] - nm0);
            sacc[j][1] = __expf(sacc[j][1] - nm0);
            sacc[j][2] = __expf(sacc[j][2] - nm1);
            sacc[j][3] = __expf(sacc[j][3] - nm1);
            ps0 += sacc[j][0] + sacc[j][1];
            ps1 += sacc[j][2] + sacc[j][3];
        }
        l0 = l0 * sc0 + ps0;
        l1 = l1 * sc1 + ps1;
#pragma unroll
        for (int j = 0; j < 16; ++j) {
            oacc[j][0] *= sc0; oacc[j][1] *= sc0;
            oacc[j][2] *= sc1; oacc[j][3] *= sc1;
        }

        uint32_t ph[4][4], pl[4][4];
#pragma unroll
        for (int c2 = 0; c2 < 4; ++c2) {
            split_pack(sacc[2 * c2][0],     sacc[2 * c2][1],     ph[c2][0], pl[c2][0]);
            split_pack(sacc[2 * c2][2],     sacc[2 * c2][3],     ph[c2][1], pl[c2][1]);
            split_pack(sacc[2 * c2 + 1][0], sacc[2 * c2 + 1][1], ph[c2][2], pl[c2][2]);
            split_pack(sacc[2 * c2 + 1][2], sacc[2 * c2 + 1][3], ph[c2][3], pl[c2][3]);
        }

#pragma unroll
        for (int c2 = 0; c2 < 4; ++c2) {
            const int krow = c2 * 16 + lr;
#pragma unroll
            for (int jj = 0; jj < 8; ++jj) {
                const uint32_t a = bv + sw256(krow, jj * 2 + lc);
                uint32_t h0, h1, h2, h3, e0, e1, e2, e3;
                ldsm_x4_t(h0, h1, h2, h3, a);
                ldsm_x4_t(e0, e1, e2, e3, a + 16384);
                uint32_t bb[2];
                bb[0] = h0; bb[1] = h1;
                mma_bf16(oacc[2 * jj], ph[c2], bb);
                mma_bf16(oacc[2 * jj], pl[c2], bb);
                bb[0] = e0; bb[1] = e1;
                mma_bf16(oacc[2 * jj], ph[c2], bb);
                bb[0] = h2; bb[1] = h3;
                mma_bf16(oacc[2 * jj + 1], ph[c2], bb);
                mma_bf16(oacc[2 * jj + 1], pl[c2], bb);
                bb[0] = e2; bb[1] = e3;
                mma_bf16(oacc[2 * jj + 1], ph[c2], bb);
            }
        }

        __syncthreads();
        if (kt + 2 < 32) load_kv(kt + 2);
    }

    l0 += __shfl_xor_sync(0xffffffffu, l0, 1);
    l0 += __shfl_xor_sync(0xffffffffu, l0, 2);
    l1 += __shfl_xor_sync(0xffffffffu, l1, 1);
    l1 += __shfl_xor_sync(0xffffffffu, l1, 2);
    const float i0 = 1.0f / l0, i1 = 1.0f / l1;

    const long long base0 = (long long)(b * L_ + r0) * HID_ + h * D_;
    const long long base1 = base0 + 8LL * HID_;
#pragma unroll
    for (int j = 0; j < 16; ++j) {
        const int d = j * 8 + 2 * t4;
        uint32_t hi0, lo0, hi1, lo1;
        split_pack(oacc[j][0] * i0, oacc[j][1] * i0, hi0, lo0);
        split_pack(oacc[j][2] * i1, oacc[j][3] * i1, hi1, lo1);
        *(uint32_t*)(Ohi + base0 + d) = hi0;
        *(uint32_t*)(Olo + base0 + d) = lo0;
        *(uint32_t*)(Ohi + base1 + d) = hi1;
        *(uint32_t*)(Olo + base1 + d) = lo1;
    }
}

// ---------------------------------------------------------------------------
static float* sym_addr(const void* sym)
{
    void* p = nullptr;
    cudaGetSymbolAddress(&p, sym);
    return (float*)p;
}

extern "C" void kernel_launch(void* const* d_in, const int* in_sizes, int n_in,
                              void* d_out, int out_size)
{
    (void)in_sizes; (void)n_in; (void)out_size;
    const float* hs = (const float*)d_in[0];
    const float* Wq = (const float*)d_in[1];
    const float* Wk = (const float*)d_in[2];
    const float* Wv = (const float*)d_in[3];
    const float* Wo = (const float*)d_in[4];
    const float* qw = (const float*)d_in[5];
    const float* kw = (const float*)d_in[6];
    const float* kb = (const float*)d_in[7];
    const float* vb = (const float*)d_in[8];
    const int*   pos  = (const int*)d_in[9];
    const unsigned int* mask = (const unsigned int*)d_in[10];
    float* out = (float*)d_out;

    float* qkv = sym_addr(g_qkv);
    __nv_bfloat16* qthi = (__nv_bfloat16*)sym_addr(g_qthi);
    __nv_bfloat16* qtlo = (__nv_bfloat16*)sym_addr(g_qtlo);
    __nv_bfloat16* kthi = (__nv_bfloat16*)sym_addr(g_kthi);
    __nv_bfloat16* ktlo = (__nv_bfloat16*)sym_addr(g_ktlo);
    __nv_bfloat16* vthi = (__nv_bfloat16*)sym_addr(g_vthi);
    __nv_bfloat16* vtlo = (__nv_bfloat16*)sym_addr(g_vtlo);
    __nv_bfloat16* ahi  = (__nv_bfloat16*)sym_addr(g_ahi);
    __nv_bfloat16* alo  = (__nv_bfloat16*)sym_addr(g_alo);
    __nv_bfloat16* whi  = (__nv_bfloat16*)sym_addr(g_whi);
    __nv_bfloat16* wlo  = (__nv_bfloat16*)sym_addr(g_wlo);

    cudaFuncSetAttribute(mma_gemm_nt,
                         cudaFuncAttributeMaxDynamicSharedMemorySize, GEMM_SMEM);
    cudaFuncSetAttribute(flash_attn,
                         cudaFuncAttributeMaxDynamicSharedMemorySize, FLASH_SMEM);

    const int nA4 = NT_ * HID_ / 4;
    const int nW4 = HID_ * HID_ / 4;
    const int WSZ = HID_ * HID_;

    // convert activations + all QKV weights (packed)
    cvt_split<<<nA4 / 256, 256>>>(hs, ahi, alo, nA4);
    cvt_split<<<nW4 / 256, 256>>>(Wq, whi, wlo, nW4);
    cvt_split<<<nW4 / 256, 256>>>(Wk, whi + WSZ, wlo + WSZ, nW4);
    cvt_split<<<nW4 / 256, 256>>>(Wv, whi + 2 * WSZ, wlo + 2 * WSZ, nW4);

    // fused QKV projection: [4096, 6144]
    mma_gemm_nt<<<dim3(3 * HID_ / 256, NT_ / 128), 256, GEMM_SMEM>>>(
        ahi, alo, whi, wlo, qkv, FAN_IN, 3 * HID_);

    qkv_post3<<<NT_, 256>>>(qkv, qw, kw, kb, vb, pos,
                            qthi, qtlo, kthi, ktlo, vthi, vtlo);

    flash_attn<<<dim3(L_ / 128, BH_), 256, FLASH_SMEM>>>(
        qthi, qtlo, kthi, ktlo, vthi, vtlo, mask, ahi, alo);

    // output projection
    cvt_split<<<nW4 / 256, 256>>>(Wo, whi, wlo, nW4);
    mma_gemm_nt<<<dim3(HID_ / 256, NT_ / 128), 256, GEMM_SMEM>>>(
        ahi, alo, whi, wlo, out, FAN_IN, HID_);
}

// round 10
// speedup vs baseline: 3.1558x; 1.0040x over previous
#include <cuda_runtime.h>
#include <cuda_bf16.h>
#include <math.h>
#include <cstdint>

// ---------------------------------------------------------------------------
// GiddAttention  B=2, L=2048, HID=2048, H=16, D=128
// Round 9: GEMM at 512 threads (4 warps/SMSP) to fix latency exposure;
// all fp32->bf16 hi/lo conversions fused into one launch (5 launches total).
// Flash attention and qkv_post3 unchanged from round 8.
// ---------------------------------------------------------------------------
namespace {
constexpr int B_   = 2;
constexpr int L_   = 2048;
constexpr int HID_ = 2048;
constexpr int H_   = 16;
constexpr int D_   = 128;
constexpr int NT_  = B_ * L_;   // 4096
constexpr int BH_  = B_ * H_;   // 32
constexpr float FAN_IN     = 0.022097086912079608f;  // 2048^-0.5
constexpr float ATTN_SCALE = 0.08838834764831845f;   // 128^-0.5
constexpr float SOFTCAP    = 30.0f;
constexpr float NEGF       = -3.402823466e38f;
constexpr float EPS_       = 1e-6f;
}

// scratch
__device__ float g_qkv[(size_t)NT_ * 3 * HID_];
__device__ __nv_bfloat16 g_qthi[NT_ * HID_];  // [BH, L, D]
__device__ __nv_bfloat16 g_qtlo[NT_ * HID_];
__device__ __nv_bfloat16 g_kthi[NT_ * HID_];
__device__ __nv_bfloat16 g_ktlo[NT_ * HID_];
__device__ __nv_bfloat16 g_vthi[NT_ * HID_];
__device__ __nv_bfloat16 g_vtlo[NT_ * HID_];
__device__ __nv_bfloat16 g_ahi[NT_ * HID_];
__device__ __nv_bfloat16 g_alo[NT_ * HID_];
__device__ __nv_bfloat16 g_whi[3 * HID_ * HID_];
__device__ __nv_bfloat16 g_wlo[3 * HID_ * HID_];
__device__ __nv_bfloat16 g_wohi[HID_ * HID_];
__device__ __nv_bfloat16 g_wolo[HID_ * HID_];

// ------------------------------ asm helpers --------------------------------
__device__ __forceinline__ uint32_t smem_u32(const void* p) {
    uint32_t a;
    asm("{ .reg .u64 t; cvta.to.shared.u64 t, %1; cvt.u32.u64 %0, t; }"
        : "=r"(a) : "l"(p));
    return a;
}
__device__ __forceinline__ void cp_async16(uint32_t dst, const void* src) {
    asm volatile("cp.async.cg.shared.global [%0], [%1], 16;"
                 :: "r"(dst), "l"(src) : "memory");
}
__device__ __forceinline__ void cp_commit() {
    asm volatile("cp.async.commit_group;" ::: "memory");
}
template <int N>
__device__ __forceinline__ void cp_wait() {
    asm volatile("cp.async.wait_group %0;" :: "n"(N) : "memory");
}
__device__ __forceinline__ void ldsm_x4(uint32_t& r0, uint32_t& r1,
                                        uint32_t& r2, uint32_t& r3, uint32_t a) {
    asm volatile("ldmatrix.sync.aligned.m8n8.x4.shared.b16 {%0,%1,%2,%3}, [%4];"
                 : "=r"(r0), "=r"(r1), "=r"(r2), "=r"(r3) : "r"(a));
}
__device__ __forceinline__ void ldsm_x4_t(uint32_t& r0, uint32_t& r1,
                                          uint32_t& r2, uint32_t& r3, uint32_t a) {
    asm volatile("ldmatrix.sync.aligned.m8n8.x4.trans.shared.b16 {%0,%1,%2,%3}, [%4];"
                 : "=r"(r0), "=r"(r1), "=r"(r2), "=r"(r3) : "r"(a));
}
__device__ __forceinline__ void mma_bf16(float* c, const uint32_t* a,
                                         const uint32_t* b) {
    asm volatile(
        "mma.sync.aligned.m16n8k16.row.col.f32.bf16.bf16.f32 "
        "{%0,%1,%2,%3}, {%4,%5,%6,%7}, {%8,%9}, {%0,%1,%2,%3};"
        : "+f"(c[0]), "+f"(c[1]), "+f"(c[2]), "+f"(c[3])
        : "r"(a[0]), "r"(a[1]), "r"(a[2]), "r"(a[3]), "r"(b[0]), "r"(b[1]));
}
__device__ __forceinline__ uint16_t bf_bits(float x) {
    __nv_bfloat16 h = __float2bfloat16(x);
    return *(uint16_t*)&h;
}
__device__ __forceinline__ float bf_val(uint16_t u) {
    __nv_bfloat16 h = *(__nv_bfloat16*)&u;
    return __bfloat162float(h);
}
__device__ __forceinline__ void split_pack(float x, float y,
                                           uint32_t& hi, uint32_t& lo) {
    uint16_t hx = bf_bits(x), hy = bf_bits(y);
    uint16_t lx = bf_bits(x - bf_val(hx)), ly = bf_bits(y - bf_val(hy));
    hi = (uint32_t)hx | ((uint32_t)hy << 16);
    lo = (uint32_t)lx | ((uint32_t)ly << 16);
}
// swizzled offset: 128B rows (col chunks of 16B)
__device__ __forceinline__ uint32_t sw128o(int row, int ck) {
    return (uint32_t)(row * 128 + (((ck ^ (row & 7)) << 4)));
}
// swizzled offset within a tile of 256B rows
__device__ __forceinline__ uint32_t sw256(int row, int ck) {
    return (uint32_t)(row * 256 + ((((ck & 7) ^ (row & 7)) | (ck & 8)) << 4));
}

// ---------------------------------------------------------------------------
// One-shot fp32 -> (hi, lo) bf16 split for hs + Wq + Wk + Wv + Wo.
// Block ranges (each block handles 256 float4):
//   [0, 8192)       hs  -> ahi/alo        (2M float4)
//   [8192, 12288)   Wq  -> whi/wlo + 0
//   [12288, 16384)  Wk  -> whi/wlo + WSZ
//   [16384, 20480)  Wv  -> whi/wlo + 2*WSZ
//   [20480, 24576)  Wo  -> wohi/wolo
// ---------------------------------------------------------------------------
__global__ __launch_bounds__(256) void cvt_all(
    const float* __restrict__ hs, const float* __restrict__ Wq,
    const float* __restrict__ Wk, const float* __restrict__ Wv,
    const float* __restrict__ Wo,
    __nv_bfloat16* __restrict__ ahi, __nv_bfloat16* __restrict__ alo,
    __nv_bfloat16* __restrict__ whi, __nv_bfloat16* __restrict__ wlo,
    __nv_bfloat16* __restrict__ wohi, __nv_bfloat16* __restrict__ wolo)
{
    const int WSZ = HID_ * HID_;
    const int blk = blockIdx.x;
    const float* src;
    __nv_bfloat16 *dhi, *dlo;
    int base;
    if (blk < 8192)      { src = hs; dhi = ahi;  dlo = alo;  base = blk; }
    else if (blk < 12288){ src = Wq; dhi = whi;  dlo = wlo;  base = blk - 8192; }
    else if (blk < 16384){ src = Wk; dhi = whi + WSZ;  dlo = wlo + WSZ;  base = blk - 12288; }
    else if (blk < 20480){ src = Wv; dhi = whi + 2*WSZ; dlo = wlo + 2*WSZ; base = blk - 16384; }
    else                 { src = Wo; dhi = wohi; dlo = wolo; base = blk - 20480; }

    const int i = base * 256 + threadIdx.x;
    float4 v = ((const float4*)src)[i];
    __nv_bfloat16 h[4], l[4];
    const float* f = &v.x;
#pragma unroll
    for (int j = 0; j < 4; ++j) {
        h[j] = __float2bfloat16(f[j]);
        l[j] = __float2bfloat16(f[j] - __bfloat162float(h[j]));
    }
    ((uint2*)dhi)[i] = *(uint2*)h;
    ((uint2*)dlo)[i] = *(uint2*)l;
}

// ---------------------------------------------------------------------------
// split-bf16 NT GEMM: C[M,N] = alpha * (Ahi+Alo)[M,2048] @ (Bhi+Blo)[N,2048]^T
// CTA tile 128x256, 512 threads (16 warps, warp tile 64x32: wy 0..1, wx 0..7).
// BK=64, double buffered.  SMEM/buffer: Ahi 16K | Alo 16K | Bhi 32K | Blo 32K.
// grid = (N/256, M/128).
// ---------------------------------------------------------------------------
static constexpr int GEMM_SMEM = 2 * 98304;

__global__ __launch_bounds__(512, 1) void mma_gemm_nt(
    const __nv_bfloat16* __restrict__ Ahi, const __nv_bfloat16* __restrict__ Alo,
    const __nv_bfloat16* __restrict__ Bhi, const __nv_bfloat16* __restrict__ Blo,
    float* __restrict__ C, float alpha, int N)
{
    extern __shared__ char smem[];
    const uint32_t sb = smem_u32(smem);
    const int tid = threadIdx.x;
    const int wid = tid >> 5, lid = tid & 31;
    const int wy = wid & 1, wx = wid >> 1;      // warp tile (wy*64, wx*32)
    const int m0 = blockIdx.y * 128, n0 = blockIdx.x * 256;
    const int K = 2048;

    const int lr8 = lid & 7, sub = lid >> 3;
    const int a_row = wy * 64 + (sub & 1) * 8 + lr8;
    const int a_col = (sub >> 1) * 8;
    const int b_row = wx * 32 + (sub >> 1) * 8 + lr8;
    const int b_col = (sub & 1) * 8;

    float acc[4][4][4] = {};

    auto load_chunk = [&](int c) {
        const uint32_t base = sb + (c & 1) * 98304;
        const int k0 = c * 64;
        // A: 128 rows x 8 chunks = 1024 units per array
#pragma unroll
        for (int v = 0; v < 2; ++v) {
            const int u = v * 512 + tid;
            const int row = u >> 3, ck = u & 7;
            const uint32_t off = sw128o(row, ck);
            const long long ga = (long long)(m0 + row) * K + k0 + ck * 8;
            cp_async16(base + off,          Ahi + ga);
            cp_async16(base + 16384 + off,  Alo + ga);
        }
        // B: 256 rows x 8 chunks = 2048 units per array
#pragma unroll
        for (int v = 0; v < 4; ++v) {
            const int u = v * 512 + tid;
            const int row = u >> 3, ck = u & 7;
            const uint32_t off = sw128o(row, ck);
            const long long gb = (long long)(n0 + row) * K + k0 + ck * 8;
            cp_async16(base + 32768 + off,  Bhi + gb);
            cp_async16(base + 65536 + off,  Blo + gb);
        }
        cp_commit();
    };

    load_chunk(0);
    for (int c = 0; c < 32; ++c) {
        if (c < 31) {
            load_chunk(c + 1);
            cp_wait<1>();
        } else {
            cp_wait<0>();
        }
        __syncthreads();
        const uint32_t base = sb + (c & 1) * 98304;
        const uint32_t sB = base + 32768;
#pragma unroll
        for (int ks = 0; ks < 4; ++ks) {
            uint32_t af[2][4][4], bf[2][4][2];
#pragma unroll
            for (int i = 0; i < 4; ++i) {
                const int row = a_row + i * 16;
                const int ck = (a_col + ks * 16) >> 3;
                ldsm_x4(af[0][i][0], af[0][i][1], af[0][i][2], af[0][i][3],
                        base + sw128o(row, ck));
                ldsm_x4(af[1][i][0], af[1][i][1], af[1][i][2], af[1][i][3],
                        base + 16384 + sw128o(row, ck));
            }
#pragma unroll
            for (int jj = 0; jj < 2; ++jj) {
                const int row = b_row + jj * 16;
                const int ck = (b_col + ks * 16) >> 3;
                uint32_t r0, r1, r2, r3;
                ldsm_x4(r0, r1, r2, r3, sB + sw128o(row, ck));
                bf[0][jj * 2][0] = r0; bf[0][jj * 2][1] = r1;
                bf[0][jj * 2 + 1][0] = r2; bf[0][jj * 2 + 1][1] = r3;
                ldsm_x4(r0, r1, r2, r3, sB + 32768 + sw128o(row, ck));
                bf[1][jj * 2][0] = r0; bf[1][jj * 2][1] = r1;
                bf[1][jj * 2 + 1][0] = r2; bf[1][jj * 2 + 1][1] = r3;
            }
#pragma unroll
            for (int i = 0; i < 4; ++i)
#pragma unroll
                for (int j = 0; j < 4; ++j)
                    mma_bf16(acc[i][j], af[0][i], bf[0][j]);
#pragma unroll
            for (int i = 0; i < 4; ++i)
#pragma unroll
                for (int j = 0; j < 4; ++j)
                    mma_bf16(acc[i][j], af[0][i], bf[1][j]);
#pragma unroll
            for (int i = 0; i < 4; ++i)
#pragma unroll
                for (int j = 0; j < 4; ++j)
                    mma_bf16(acc[i][j], af[1][i], bf[0][j]);
        }
        __syncthreads();
    }

    const int g = lid >> 2, t = lid & 3;
#pragma unroll
    for (int i = 0; i < 4; ++i) {
        const int row = m0 + wy * 64 + i * 16 + g;
#pragma unroll
        for (int j = 0; j < 4; ++j) {
            const int col = n0 + wx * 32 + j * 8 + t * 2;
            float2 v0 = make_float2(alpha * acc[i][j][0], alpha * acc[i][j][1]);
            float2 v1 = make_float2(alpha * acc[i][j][2], alpha * acc[i][j][3]);
            *(float2*)(C + (long long)row * N + col)       = v0;
            *(float2*)(C + (long long)(row + 8) * N + col) = v1;
        }
    }
}

// ---------------------------------------------------------------------------
// Fused per-token post for q|k|v packed rows (unchanged from round 8).
// ---------------------------------------------------------------------------
__global__ __launch_bounds__(256) void qkv_post3(
    const float* __restrict__ QKV,
    const float* __restrict__ qw, const float* __restrict__ kw,
    const float* __restrict__ kb, const float* __restrict__ vb,
    const int* __restrict__ positions,
    __nv_bfloat16* __restrict__ Qhi, __nv_bfloat16* __restrict__ Qlo,
    __nv_bfloat16* __restrict__ Khi, __nv_bfloat16* __restrict__ Klo,
    __nv_bfloat16* __restrict__ Vhi, __nv_bfloat16* __restrict__ Vlo)
{
    __shared__ float sh[3 * HID_];
    __shared__ float redq[8], redk[8];
    __shared__ float shInv[64];

    const int t = blockIdx.x;
    const int b = t >> 11;
    const int l = t & (L_ - 1);
    const float* x = QKV + (long long)t * (3 * HID_);

    if (threadIdx.x < 64)
        shInv[threadIdx.x] =
            (float)exp2(-(double)threadIdx.x * 0.20762050593046014);

    float sq = 0.f, sk = 0.f;
    for (int j = threadIdx.x; j < 2 * HID_; j += 256) {
        float v = x[j];
        sh[j] = v;
        if (j < HID_) sq += v * v; else sk += v * v;
    }
    for (int j = 2 * HID_ + threadIdx.x; j < 3 * HID_; j += 256)
        sh[j] = x[j];
#pragma unroll
    for (int o = 16; o; o >>= 1) {
        sq += __shfl_xor_sync(0xffffffffu, sq, o);
        sk += __shfl_xor_sync(0xffffffffu, sk, o);
    }
    if ((threadIdx.x & 31) == 0) {
        redq[threadIdx.x >> 5] = sq;
        redk[threadIdx.x >> 5] = sk;
    }
    __syncthreads();
    float tq = redq[0] + redq[1] + redq[2] + redq[3] +
               redq[4] + redq[5] + redq[6] + redq[7];
    float tk = redk[0] + redk[1] + redk[2] + redk[3] +
               redk[4] + redk[5] + redk[6] + redk[7];
    const float rsq = rsqrtf(tq * (1.0f / HID_) + EPS_);
    const float rsk = rsqrtf(tk * (1.0f / HID_) + EPS_);
    const float p = (float)positions[t];

    for (int j = threadIdx.x; j < HID_; j += 256) {
        const int h = j >> 7;
        const int d = j & 127;
        const long long oi = (((long long)(b * H_ + h)) * L_ + l) * D_ + d;
        const int partner = (d < 64) ? j + 64 : j - 64;
        const float ang = p * shInv[d & 63];
        const float co = cosf(ang);
        const float si = sinf(ang);

        {
            const float y  = sh[j] * rsq * (1.f + qw[j]);
            const float y2 = sh[partner] * rsq * (1.f + qw[partner]);
            float o = ((d < 64) ? (y * co - y2 * si) : (y * co + y2 * si)) * ATTN_SCALE;
            __nv_bfloat16 hi = __float2bfloat16(o);
            Qhi[oi] = hi;
            Qlo[oi] = __float2bfloat16(o - __bfloat162float(hi));
        }
        {
            const float y  = sh[HID_ + j] * rsk * (1.f + kw[j]);
            const float y2 = sh[HID_ + partner] * rsk * (1.f + kw[partner]);
            float o = ((d < 64) ? (y * co - y2 * si) : (y * co + y2 * si))
                      + kb[(h << 7) + d];
            __nv_bfloat16 hi = __float2bfloat16(o);
            Khi[oi] = hi;
            Klo[oi] = __float2bfloat16(o - __bfloat162float(hi));
        }
        {
            float o = sh[2 * HID_ + j] + vb[(h << 7) + d];
            __nv_bfloat16 hi = __float2bfloat16(o);
            Vhi[oi] = hi;
            Vlo[oi] = __float2bfloat16(o - __bfloat162float(hi));
        }
    }
}

// ---------------------------------------------------------------------------
// Flash attention (unchanged from round 8): grid (L/128, BH), 256 threads.
// ---------------------------------------------------------------------------
static constexpr int FLASH_SMEM = 196608;

__global__ __launch_bounds__(256, 1) void flash_attn(
    const __nv_bfloat16* __restrict__ Qhi, const __nv_bfloat16* __restrict__ Qlo,
    const __nv_bfloat16* __restrict__ Khi, const __nv_bfloat16* __restrict__ Klo,
    const __nv_bfloat16* __restrict__ Vhi, const __nv_bfloat16* __restrict__ Vlo,
    const unsigned int* __restrict__ mask,
    __nv_bfloat16* __restrict__ Ohi, __nv_bfloat16* __restrict__ Olo)
{
    extern __shared__ char smem[];
    const uint32_t sb = smem_u32(smem);
    const int tid = threadIdx.x, wid = tid >> 5, lid = tid & 31;
    const int bh = blockIdx.y, b = bh >> 4, h = bh & 15;
    const int q0 = blockIdx.x * 128;

    const long long qoff = ((long long)bh * L_ + q0) * D_;
    const long long koff = (long long)bh * L_ * D_;

#pragma unroll
    for (int v = 0; v < 8; ++v) {
        const int idx = v * 256 + tid;
        const int row = idx >> 4, ck = idx & 15;
        const uint32_t off = sw256(row, ck);
        cp_async16(sb + off,          Qhi + qoff + row * D_ + ck * 8);
        cp_async16(sb + 32768 + off,  Qlo + qoff + row * D_ + ck * 8);
    }
    auto load_kv = [&](int kt) {
        const uint32_t bk = 65536 + (kt & 1) * 32768;
        const uint32_t bv = 131072 + (kt & 1) * 32768;
#pragma unroll
        for (int v = 0; v < 4; ++v) {
            const int idx = v * 256 + tid;
            const int row = idx >> 4, ck = idx & 15;
            const uint32_t off = sw256(row, ck);
            const long long gg = koff + (long long)(kt * 64 + row) * D_ + ck * 8;
            cp_async16(sb + bk + off,          Khi + gg);
            cp_async16(sb + bk + 16384 + off,  Klo + gg);
            cp_async16(sb + bv + off,          Vhi + gg);
            cp_async16(sb + bv + 16384 + off,  Vlo + gg);
        }
        cp_commit();
    };
    load_kv(0);
    load_kv(1);

    cp_wait<1>();
    __syncthreads();

    const int g = lid >> 2, t4 = lid & 3;
    const int lr = lid & 15, lc = lid >> 4;

    uint32_t qh[8][4], ql[8][4];
    {
        const int row = wid * 16 + lr;
#pragma unroll
        for (int kc = 0; kc < 8; ++kc) {
            const uint32_t a = sb + sw256(row, kc * 2 + lc);
            ldsm_x4(qh[kc][0], qh[kc][1], qh[kc][2], qh[kc][3], a);
            ldsm_x4(ql[kc][0], ql[kc][1], ql[kc][2], ql[kc][3], a + 32768);
        }
    }

    float oacc[16][4];
#pragma unroll
    for (int j = 0; j < 16; ++j)
        oacc[j][0] = oacc[j][1] = oacc[j][2] = oacc[j][3] = 0.f;
    float m0 = NEGF, m1 = NEGF, l0 = 0.f, l1 = 0.f;

    const int r0 = q0 + wid * 16 + g;
    const unsigned int* mrow0 = mask + (long long)b * L_ * L_ + (long long)r0 * L_;
    const unsigned int* mrow1 = mrow0 + 8 * L_;

    for (int kt = 0; kt < 32; ++kt) {
        if (kt == 31) cp_wait<0>(); else cp_wait<1>();
        __syncthreads();
        const uint32_t bk = sb + 65536 + (kt & 1) * 32768;
        const uint32_t bv = sb + 131072 + (kt & 1) * 32768;

        float sacc[8][4];
#pragma unroll
        for (int j = 0; j < 8; ++j)
            sacc[j][0] = sacc[j][1] = sacc[j][2] = sacc[j][3] = 0.f;

#pragma unroll
        for (int kc = 0; kc < 8; ++kc) {
            const int ck = kc * 2 + lc;
#pragma unroll
            for (int jj = 0; jj < 4; ++jj) {
                const int row = jj * 16 + lr;
                const uint32_t a = bk + sw256(row, ck);
                uint32_t h0, h1, h2, h3, e0, e1, e2, e3;
                ldsm_x4(h0, h1, h2, h3, a);
                ldsm_x4(e0, e1, e2, e3, a + 16384);
                uint32_t bb[2];
                bb[0] = h0; bb[1] = h2;
                mma_bf16(sacc[2 * jj], qh[kc], bb);
                mma_bf16(sacc[2 * jj], ql[kc], bb);
                bb[0] = e0; bb[1] = e2;
                mma_bf16(sacc[2 * jj], qh[kc], bb);
                bb[0] = h1; bb[1] = h3;
                mma_bf16(sacc[2 * jj + 1], qh[kc], bb);
                mma_bf16(sacc[2 * jj + 1], ql[kc], bb);
                bb[0] = e1; bb[1] = e3;
                mma_bf16(sacc[2 * jj + 1], qh[kc], bb);
            }
        }

        const int kb2 = kt * 64;
#pragma unroll
        for (int j = 0; j < 8; ++j) {
            const int kc2 = kb2 + j * 8 + 2 * t4;
            const uint2 ma = *(const uint2*)(mrow0 + kc2);
            const uint2 mb = *(const uint2*)(mrow1 + kc2);
#pragma unroll
            for (int e = 0; e < 4; ++e) {
                float s = sacc[j][e];
                const float tt = __expf(s * (2.0f / SOFTCAP));
                s = SOFTCAP * __fdividef(tt - 1.0f, tt + 1.0f);
                const unsigned int mm = (e == 0) ? ma.x : (e == 1) ? ma.y
                                        : (e == 2) ? mb.x : mb.y;
                sacc[j][e] = (mm != 0u) ? s : NEGF;
            }
        }

        float rx0 = NEGF, rx1 = NEGF;
#pragma unroll
        for (int j = 0; j < 8; ++j) {
            rx0 = fmaxf(rx0, fmaxf(sacc[j][0], sacc[j][1]));
            rx1 = fmaxf(rx1, fmaxf(sacc[j][2], sacc[j][3]));
        }
        rx0 = fmaxf(rx0, __shfl_xor_sync(0xffffffffu, rx0, 1));
        rx0 = fmaxf(rx0, __shfl_xor_sync(0xffffffffu, rx0, 2));
        rx1 = fmaxf(rx1, __shfl_xor_sync(0xffffffffu, rx1, 1));
        rx1 = fmaxf(rx1, __shfl_xor_sync(0xffffffffu, rx1, 2));
        const float nm0 = fmaxf(m0, rx0), nm1 = fmaxf(m1, rx1);
        const float sc0 = __expf(m0 - nm0), sc1 = __expf(m1 - nm1);
        m0 = nm0; m1 = nm1;
        float ps0 = 0.f, ps1 = 0.f;
#pragma unroll
        for (int j = 0; j < 8; ++j) {
            sacc[j][0] = __expf(sacc[j][0] - nm0);
            sacc[j][1] = __expf(sacc[j][1] - nm0);
            sacc[j][2] = __expf(sacc[j][2] - nm1);
            sacc[j][3] = __expf(sacc[j][3] - nm1);
            ps0 += sacc[j][0] + sacc[j][1];
            ps1 += sacc[j][2] + sacc[j][3];
        }
        l0 = l0 * sc0 + ps0;
        l1 = l1 * sc1 + ps1;
#pragma unroll
        for (int j = 0; j < 16; ++j) {
            oacc[j][0] *= sc0; oacc[j][1] *= sc0;
            oacc[j][2] *= sc1; oacc[j][3] *= sc1;
        }

        uint32_t ph[4][4], pl[4][4];
#pragma unroll
        for (int c2 = 0; c2 < 4; ++c2) {
            split_pack(sacc[2 * c2][0],     sacc[2 * c2][1],     ph[c2][0], pl[c2][0]);
            split_pack(sacc[2 * c2][2],     sacc[2 * c2][3],     ph[c2][1], pl[c2][1]);
            split_pack(sacc[2 * c2 + 1][0], sacc[2 * c2 + 1][1], ph[c2][2], pl[c2][2]);
            split_pack(sacc[2 * c2 + 1][2], sacc[2 * c2 + 1][3], ph[c2][3], pl[c2][3]);
        }

#pragma unroll
        for (int c2 = 0; c2 < 4; ++c2) {
            const int krow = c2 * 16 + lr;
#pragma unroll
            for (int jj = 0; jj < 8; ++jj) {
                const uint32_t a = bv + sw256(krow, jj * 2 + lc);
                uint32_t h0, h1, h2, h3, e0, e1, e2, e3;
                ldsm_x4_t(h0, h1, h2, h3, a);
                ldsm_x4_t(e0, e1, e2, e3, a + 16384);
                uint32_t bb[2];
                bb[0] = h0; bb[1] = h1;
                mma_bf16(oacc[2 * jj], ph[c2], bb);
                mma_bf16(oacc[2 * jj], pl[c2], bb);
                bb[0] = e0; bb[1] = e1;
                mma_bf16(oacc[2 * jj], ph[c2], bb);
                bb[0] = h2; bb[1] = h3;
                mma_bf16(oacc[2 * jj + 1], ph[c2], bb);
                mma_bf16(oacc[2 * jj + 1], pl[c2], bb);
                bb[0] = e2; bb[1] = e3;
                mma_bf16(oacc[2 * jj + 1], ph[c2], bb);
            }
        }

        __syncthreads();
        if (kt + 2 < 32) load_kv(kt + 2);
    }

    l0 += __shfl_xor_sync(0xffffffffu, l0, 1);
    l0 += __shfl_xor_sync(0xffffffffu, l0, 2);
    l1 += __shfl_xor_sync(0xffffffffu, l1, 1);
    l1 += __shfl_xor_sync(0xffffffffu, l1, 2);
    const float i0 = 1.0f / l0, i1 = 1.0f / l1;

    const long long base0 = (long long)(b * L_ + r0) * HID_ + h * D_;
    const long long base1 = base0 + 8LL * HID_;
#pragma unroll
    for (int j = 0; j < 16; ++j) {
        const int d = j * 8 + 2 * t4;
        uint32_t hi0, lo0, hi1, lo1;
        split_pack(oacc[j][0] * i0, oacc[j][1] * i0, hi0, lo0);
        split_pack(oacc[j][2] * i1, oacc[j][3] * i1, hi1, lo1);
        *(uint32_t*)(Ohi + base0 + d) = hi0;
        *(uint32_t*)(Olo + base0 + d) = lo0;
        *(uint32_t*)(Ohi + base1 + d) = hi1;
        *(uint32_t*)(Olo + base1 + d) = lo1;
    }
}

// ---------------------------------------------------------------------------
static float* sym_addr(const void* sym)
{
    void* p = nullptr;
    cudaGetSymbolAddress(&p, sym);
    return (float*)p;
}

extern "C" void kernel_launch(void* const* d_in, const int* in_sizes, int n_in,
                              void* d_out, int out_size)
{
    (void)in_sizes; (void)n_in; (void)out_size;
    const float* hs = (const float*)d_in[0];
    const float* Wq = (const float*)d_in[1];
    const float* Wk = (const float*)d_in[2];
    const float* Wv = (const float*)d_in[3];
    const float* Wo = (const float*)d_in[4];
    const float* qw = (const float*)d_in[5];
    const float* kw = (const float*)d_in[6];
    const float* kb = (const float*)d_in[7];
    const float* vb = (const float*)d_in[8];
    const int*   pos  = (const int*)d_in[9];
    const unsigned int* mask = (const unsigned int*)d_in[10];
    float* out = (float*)d_out;

    float* qkv = sym_addr(g_qkv);
    __nv_bfloat16* qthi = (__nv_bfloat16*)sym_addr(g_qthi);
    __nv_bfloat16* qtlo = (__nv_bfloat16*)sym_addr(g_qtlo);
    __nv_bfloat16* kthi = (__nv_bfloat16*)sym_addr(g_kthi);
    __nv_bfloat16* ktlo = (__nv_bfloat16*)sym_addr(g_ktlo);
    __nv_bfloat16* vthi = (__nv_bfloat16*)sym_addr(g_vthi);
    __nv_bfloat16* vtlo = (__nv_bfloat16*)sym_addr(g_vtlo);
    __nv_bfloat16* ahi  = (__nv_bfloat16*)sym_addr(g_ahi);
    __nv_bfloat16* alo  = (__nv_bfloat16*)sym_addr(g_alo);
    __nv_bfloat16* whi  = (__nv_bfloat16*)sym_addr(g_whi);
    __nv_bfloat16* wlo  = (__nv_bfloat16*)sym_addr(g_wlo);
    __nv_bfloat16* wohi = (__nv_bfloat16*)sym_addr(g_wohi);
    __nv_bfloat16* wolo = (__nv_bfloat16*)sym_addr(g_wolo);

    cudaFuncSetAttribute(mma_gemm_nt,
                         cudaFuncAttributeMaxDynamicSharedMemorySize, GEMM_SMEM);
    cudaFuncSetAttribute(flash_attn,
                         cudaFuncAttributeMaxDynamicSharedMemorySize, FLASH_SMEM);

    // one launch converts everything
    cvt_all<<<24576, 256>>>(hs, Wq, Wk, Wv, Wo,
                            ahi, alo, whi, wlo, wohi, wolo);

    // fused QKV projection: [4096, 6144]
    mma_gemm_nt<<<dim3(3 * HID_ / 256, NT_ / 128), 512, GEMM_SMEM>>>(
        ahi, alo, whi, wlo, qkv, FAN_IN, 3 * HID_);

    qkv_post3<<<NT_, 256>>>(qkv, qw, kw, kb, vb, pos,
                            qthi, qtlo, kthi, ktlo, vthi, vtlo);

    flash_attn<<<dim3(L_ / 128, BH_), 256, FLASH_SMEM>>>(
        qthi, qtlo, kthi, ktlo, vthi, vtlo, mask, ahi, alo);

    // output projection
    mma_gemm_nt<<<dim3(HID_ / 256, NT_ / 128), 512, GEMM_SMEM>>>(
        ahi, alo, wohi, wolo, out, FAN_IN, HID_);
}